// round 2
// baseline (speedup 1.0000x reference)
#include <cuda_runtime.h>
#include <math.h>

// Problem constants
#define B 4
#define L 256
#define D 512
#define O 128
#define DP1 513              // D+1 (bias-augmented)
#define BX (B*L)             // 1024 combined (b,x) rows

// Scratch (static device globals; no runtime allocation)
__device__ float g_T[(size_t)BX * O * DP1];   // T[bx][o][j], j contiguous  (~269 MB)
__device__ float g_L1[BX * O];                // w1*(x1@Wlin[:D] + b_lin)
__device__ float g_L2[BX * O];                // w1*(x2@Wlin[D:])

// ---------------------------------------------------------------------------
// Stage 1: T[bx, o, j] = sum_i x1b[bx, i] * W_bil[o, i, j]
// Batched SGEMM: M=1024, N=513, K=513, batch o=128.
// Block tile 64x64, BK=16, 256 threads, 4x4 per thread.
// ---------------------------------------------------------------------------
__global__ __launch_bounds__(256, 2)
void stage1_kernel(const float* __restrict__ x1, const float* __restrict__ Wb)
{
    const int o  = blockIdx.z;
    const int m0 = blockIdx.y * 64;
    const int n0 = blockIdx.x * 64;
    const float* __restrict__ Wo = Wb + (size_t)o * DP1 * DP1;

    __shared__ float As[16][68];   // As[k][m] (transposed)
    __shared__ float Bs[16][68];   // Bs[k][n]

    const int tid = threadIdx.x;
    const int ty = tid >> 4;       // 0..15
    const int tx = tid & 15;       // 0..15

    // A-load mapping: 4 elems per thread, (m = tid/4, k = (tid&3)*4 + i)
    const int a_m = tid >> 2;
    const int a_k = (tid & 3) * 4;
    // B-load mapping: (k = tid/16, n = (tid&15)*4 + i)
    const int b_k = tid >> 4;
    const int b_n = (tid & 15) * 4;

    float acc[4][4] = {};

    for (int k0 = 0; k0 < DP1; k0 += 16) {
        // Load A tile (x1 augmented with ones column at i==512)
        {
            const int mg = m0 + a_m;
            #pragma unroll
            for (int i = 0; i < 4; i++) {
                const int kg = k0 + a_k + i;
                float v;
                if (kg < D)        v = x1[(size_t)mg * D + kg];
                else if (kg == D)  v = 1.0f;
                else               v = 0.0f;
                As[a_k + i][a_m] = v;
            }
        }
        // Load B tile from W_bil[o]
        {
            const int kg = k0 + b_k;
            const bool krow = (kg < DP1);
            #pragma unroll
            for (int i = 0; i < 4; i++) {
                const int ng = n0 + b_n + i;
                float v = 0.0f;
                if (krow && ng < DP1) v = Wo[(size_t)kg * DP1 + ng];
                Bs[b_k][b_n + i] = v;
            }
        }
        __syncthreads();

        #pragma unroll
        for (int k = 0; k < 16; k++) {
            float ra[4], rb[4];
            #pragma unroll
            for (int i = 0; i < 4; i++) ra[i] = As[k][ty * 4 + i];
            #pragma unroll
            for (int j = 0; j < 4; j++) rb[j] = Bs[k][tx * 4 + j];
            #pragma unroll
            for (int i = 0; i < 4; i++)
                #pragma unroll
                for (int j = 0; j < 4; j++)
                    acc[i][j] = fmaf(ra[i], rb[j], acc[i][j]);
        }
        __syncthreads();
    }

    // Epilogue: write T[m][o][n]
    #pragma unroll
    for (int i = 0; i < 4; i++) {
        const int m = m0 + ty * 4 + i;
        float* Trow = g_T + ((size_t)m * O + o) * DP1;
        #pragma unroll
        for (int j = 0; j < 4; j++) {
            const int n = n0 + tx * 4 + j;
            if (n < DP1) Trow[n] = acc[i][j];
        }
    }
}

// ---------------------------------------------------------------------------
// Linear part: L1[m,o] = w1*(x1[m]@Wlin[:D,o] + b_lin[o]); L2[m,o] = w1*(x2[m]@Wlin[D:,o])
// One block per (which, m), 128 threads (one per o).
// ---------------------------------------------------------------------------
__global__ __launch_bounds__(128)
void lin_kernel(const float* __restrict__ x1, const float* __restrict__ x2,
                const float* __restrict__ Wlin, const float* __restrict__ b_lin,
                const float* __restrict__ bw)
{
    const int idx   = blockIdx.x;
    const int which = idx >> 10;       // 0 -> L1, 1 -> L2
    const int m     = idx & 1023;
    const int o     = threadIdx.x;

    const float* xr = (which ? x2 : x1) + (size_t)m * D;
    const float* Wp = Wlin + (which ? (size_t)D * O : 0);

    __shared__ float xs[D];
    for (int d = o; d < D; d += O) xs[d] = xr[d];
    __syncthreads();

    float acc = 0.0f;
    #pragma unroll 8
    for (int d = 0; d < D; d++)
        acc = fmaf(xs[d], Wp[(size_t)d * O + o], acc);

    const float e0 = expf(bw[0]), e1 = expf(bw[1]);
    const float w1 = e1 / (e0 + e1);

    if (which) g_L2[m * O + o] = w1 * acc;
    else       g_L1[m * O + o] = w1 * (acc + b_lin[o]);
}

// ---------------------------------------------------------------------------
// Stage 2: out[bx, y, o] = w0 * sum_j T[bx,o,j]*x2b[b,y,j] + L1[bx,o] + L2[b*L+y,o]
// Per-bx GEMM: M=256 (y), N=128 (o), K=513. Block tile 64x64, BK=16.
// Grid: (o_tiles=2, y_tiles=4, bx=1024)
// ---------------------------------------------------------------------------
__global__ __launch_bounds__(256, 2)
void stage2_kernel(const float* __restrict__ x2, const float* __restrict__ bw,
                   float* __restrict__ out)
{
    const int bx = blockIdx.z;
    const int b  = bx >> 8;
    const int y0 = blockIdx.y * 64;
    const int o0 = blockIdx.x * 64;

    const float* __restrict__ Tb = g_T + (size_t)bx * O * DP1;

    __shared__ float As[16][68];   // As[j][y]
    __shared__ float Bs[16][68];   // Bs[j][o]

    const int tid = threadIdx.x;
    const int ty = tid >> 4;
    const int tx = tid & 15;

    const int a_m = tid >> 2;          // y within tile
    const int a_k = (tid & 3) * 4;
    const int b_o = tid >> 2;          // o within tile
    const int b_j = (tid & 3) * 4;

    float acc[4][4] = {};

    for (int k0 = 0; k0 < DP1; k0 += 16) {
        // Load A = x2b[b, y, j] (ones at j==512)
        {
            const int yg = y0 + a_m;
            const size_t base = ((size_t)b * L + yg) * D;
            #pragma unroll
            for (int i = 0; i < 4; i++) {
                const int jg = k0 + a_k + i;
                float v;
                if (jg < D)        v = x2[base + jg];
                else if (jg == D)  v = 1.0f;
                else               v = 0.0f;
                As[a_k + i][a_m] = v;
            }
        }
        // Load B = T[bx, o, j] (transpose into Bs[j][o])
        {
            const int og = o0 + b_o;
            const float* Tro = Tb + (size_t)og * DP1;
            #pragma unroll
            for (int i = 0; i < 4; i++) {
                const int jg = k0 + b_j + i;
                float v = (jg < DP1) ? Tro[jg] : 0.0f;
                Bs[b_j + i][b_o] = v;
            }
        }
        __syncthreads();

        #pragma unroll
        for (int k = 0; k < 16; k++) {
            float ra[4], rb[4];
            #pragma unroll
            for (int i = 0; i < 4; i++) ra[i] = As[k][ty * 4 + i];
            #pragma unroll
            for (int j = 0; j < 4; j++) rb[j] = Bs[k][tx * 4 + j];
            #pragma unroll
            for (int i = 0; i < 4; i++)
                #pragma unroll
                for (int j = 0; j < 4; j++)
                    acc[i][j] = fmaf(ra[i], rb[j], acc[i][j]);
        }
        __syncthreads();
    }

    const float e0 = expf(bw[0]), e1 = expf(bw[1]);
    const float w0 = e0 / (e0 + e1);

    // Epilogue: out[bx, y, o] contiguous in o — vectorized 4-wide writes
    #pragma unroll
    for (int i = 0; i < 4; i++) {
        const int y = y0 + ty * 4 + i;
        const int yg = b * L + y;
        float4 r;
        const int oc = o0 + tx * 4;
        r.x = w0 * acc[i][0] + g_L1[bx * O + oc + 0] + g_L2[yg * O + oc + 0];
        r.y = w0 * acc[i][1] + g_L1[bx * O + oc + 1] + g_L2[yg * O + oc + 1];
        r.z = w0 * acc[i][2] + g_L1[bx * O + oc + 2] + g_L2[yg * O + oc + 2];
        r.w = w0 * acc[i][3] + g_L1[bx * O + oc + 3] + g_L2[yg * O + oc + 3];
        *reinterpret_cast<float4*>(out + ((size_t)bx * L + y) * O + oc) = r;
    }
}

// ---------------------------------------------------------------------------
extern "C" void kernel_launch(void* const* d_in, const int* in_sizes, int n_in,
                              void* d_out, int out_size)
{
    const float* x1    = (const float*)d_in[0];
    const float* x2    = (const float*)d_in[1];
    const float* bw    = (const float*)d_in[2];
    const float* W_bil = (const float*)d_in[3];
    const float* W_lin = (const float*)d_in[4];
    const float* b_lin = (const float*)d_in[5];
    float* out = (float*)d_out;

    // Stage 1: T = x1b @ W_bil   (grid: 9 n-tiles x 16 m-tiles x 128 o)
    stage1_kernel<<<dim3(9, 16, O), 256>>>(x1, W_bil);

    // Linear precompute (2048 blocks: 1024 for L1, 1024 for L2)
    lin_kernel<<<2048, 128>>>(x1, x2, W_lin, b_lin, bw);

    // Stage 2: out = w0 * (T @ x2b^T) + linear   (grid: 2 o-tiles x 4 y-tiles x 1024 bx)
    stage2_kernel<<<dim3(2, 4, BX), 256>>>(x2, bw, out);
}

// round 5
// speedup vs baseline: 3.0980x; 3.0980x over previous
#include <cuda_runtime.h>
#include <cuda_bf16.h>
#include <cstdint>
#include <cstddef>
#include <math.h>

#define B 4
#define L 256
#define D 512
#define O 128
#define BX 1024
#define WSTRIDE 263169       // 513*513

// ---------------- device scratch (static, no runtime alloc) ----------------
__device__ __nv_bfloat16 g_x1hi[BX * D];
__device__ __nv_bfloat16 g_x1lo[BX * D];
__device__ __nv_bfloat16 g_x2hi[BX * D];
__device__ __nv_bfloat16 g_x2lo[BX * D];
__device__ __nv_bfloat16 g_Whi[(size_t)O * D * D];   // Wt[o][j][i]
__device__ __nv_bfloat16 g_Wlo[(size_t)O * D * D];
__device__ __nv_bfloat16 g_Thi[(size_t)BX * O * D];  // T[bx][o][j]
__device__ __nv_bfloat16 g_Tlo[(size_t)BX * O * D];
__device__ float g_colWt[D * O];   // colWt[i][o] = W[o][i][512]
__device__ float g_rowWt[D * O];   // rowWt[j][o] = W[o][512][j]
__device__ float g_A1[BX * O];     // w0*colterm + w1*(lin1 + b_lin)
__device__ float g_A2[BX * O];     // w0*(rowterm + corner) + w1*lin2

// ---------------- low-level helpers ----------------
__device__ __forceinline__ uint32_t s2u(const void* p) {
    uint32_t a;
    asm("{ .reg .u64 t; cvta.to.shared.u64 t, %1; cvt.u32.u64 %0, t; }" : "=r"(a) : "l"(p));
    return a;
}
__device__ __forceinline__ void cpa16(uint32_t d, const void* s) {
    asm volatile("cp.async.cg.shared.global [%0], [%1], 16;" :: "r"(d), "l"(s) : "memory");
}
#define CP_COMMIT() asm volatile("cp.async.commit_group;" ::: "memory")

__device__ __forceinline__ void ldsm_x4(uint32_t a, uint32_t r[4]) {
    asm volatile("ldmatrix.sync.aligned.m8n8.x4.shared.b16 {%0,%1,%2,%3}, [%4];"
                 : "=r"(r[0]), "=r"(r[1]), "=r"(r[2]), "=r"(r[3]) : "r"(a));
}
__device__ __forceinline__ void mma16816(float c[4], const uint32_t a[4], const uint32_t b[2]) {
    asm volatile(
        "mma.sync.aligned.m16n8k16.row.col.f32.bf16.bf16.f32 "
        "{%0,%1,%2,%3}, {%4,%5,%6,%7}, {%8,%9}, {%0,%1,%2,%3};"
        : "+f"(c[0]), "+f"(c[1]), "+f"(c[2]), "+f"(c[3])
        : "r"(a[0]), "r"(a[1]), "r"(a[2]), "r"(a[3]), "r"(b[0]), "r"(b[1]));
}

// Tile geometry: 128 rows x 32 bf16 (64B) per k-chunk, 80B row stride (16B pad).
// 4 tiles per buffer (Ah, Al, Bh, Bl), 2 buffers.
#define TILE_B   10240      // 128 * 80
#define BUF_B    40960      // 4 tiles
#define GSMEM    81920      // 2 buffers

// 256 threads cooperatively cp.async one 128x32 tile (row stride in gmem = 512 bf16)
__device__ __forceinline__ void load_tile80(uint32_t dst, const __nv_bfloat16* src,
                                            int tid, int k0) {
    #pragma unroll
    for (int it = 0; it < 2; it++) {
        int op = it * 256 + tid;            // 0..511
        int row = op >> 2, ch = op & 3;
        cpa16(dst + row * 80 + ch * 16,
              (const char*)src + (size_t)row * 1024 + (size_t)k0 * 2 + ch * 16);
    }
}

// One k16 step: 12 ldmatrix.x4 + 48 mma per warp (3 split terms)
__device__ __forceinline__ void compute_k16(uint32_t base, int kk, int lane,
                                            int warp_m, int warp_n, float acc[4][4][4]) {
    uint32_t ah[4][4], al[4][4];
    #pragma unroll
    for (int mt = 0; mt < 4; mt++) {
        int row = warp_m * 64 + mt * 16 + (lane & 7) + ((lane >> 3) & 1) * 8;
        int col = kk + (lane >> 4) * 8;
        uint32_t ad = base + row * 80 + col * 2;
        ldsm_x4(ad, ah[mt]);
        ldsm_x4(ad + TILE_B, al[mt]);
    }
    uint32_t bh[2][4], bl[2][4];
    #pragma unroll
    for (int p = 0; p < 2; p++) {
        int n = warp_n * 32 + p * 16 + (lane & 7) + (lane >> 4) * 8;
        int col = kk + ((lane >> 3) & 1) * 8;
        uint32_t bd = base + 2 * TILE_B + n * 80 + col * 2;
        ldsm_x4(bd, bh[p]);
        ldsm_x4(bd + TILE_B, bl[p]);
    }
    #pragma unroll
    for (int mt = 0; mt < 4; mt++)
        #pragma unroll
        for (int nt = 0; nt < 4; nt++) {
            const uint32_t* bhf = &bh[nt >> 1][(nt & 1) * 2];
            const uint32_t* blf = &bl[nt >> 1][(nt & 1) * 2];
            mma16816(acc[mt][nt], ah[mt], bhf);
            mma16816(acc[mt][nt], ah[mt], blf);
            mma16816(acc[mt][nt], al[mt], bhf);
        }
}

// C[128x128] += Ah*Bh^T + Ah*Bl^T + Al*Bh^T over K=512 (A,B K-major, ld=512)
__device__ __forceinline__ void gemm_loop(uint32_t sb, int tid,
    const __nv_bfloat16* Ah, const __nv_bfloat16* Al,
    const __nv_bfloat16* Bh, const __nv_bfloat16* Bl,
    float acc[4][4][4])
{
    const int lane = tid & 31;
    const int warp_m = (tid >> 5) & 1, warp_n = tid >> 6;

    // prologue: chunk 0 -> buffer 0
    {
        load_tile80(sb,               Ah, tid, 0);
        load_tile80(sb + TILE_B,      Al, tid, 0);
        load_tile80(sb + 2 * TILE_B,  Bh, tid, 0);
        load_tile80(sb + 3 * TILE_B,  Bl, tid, 0);
        CP_COMMIT();
    }

    #pragma unroll 1
    for (int c = 0; c < 16; c++) {
        if (c + 1 < 16) {
            const uint32_t nb = sb + ((c + 1) & 1) * BUF_B;
            const int k0 = (c + 1) * 32;
            load_tile80(nb,              Ah, tid, k0);
            load_tile80(nb + TILE_B,     Al, tid, k0);
            load_tile80(nb + 2 * TILE_B, Bh, tid, k0);
            load_tile80(nb + 3 * TILE_B, Bl, tid, k0);
            CP_COMMIT();
            asm volatile("cp.async.wait_group 1;" ::: "memory");
        } else {
            asm volatile("cp.async.wait_group 0;" ::: "memory");
        }
        __syncthreads();
        const uint32_t base = sb + (c & 1) * BUF_B;
        compute_k16(base, 0,  lane, warp_m, warp_n, acc);
        compute_k16(base, 16, lane, warp_m, warp_n, acc);
        __syncthreads();
    }
}

// ---------------- pre-pass kernels ----------------
__global__ __launch_bounds__(256)
void prep_x(const float* __restrict__ x1, const float* __restrict__ x2)
{
    int i = blockIdx.x * 256 + threadIdx.x;
    if (i >= BX * D) return;
    float v = x1[i];
    __nv_bfloat16 h = __float2bfloat16(v);
    g_x1hi[i] = h; g_x1lo[i] = __float2bfloat16(v - __bfloat162float(h));
    v = x2[i];
    h = __float2bfloat16(v);
    g_x2hi[i] = h; g_x2lo[i] = __float2bfloat16(v - __bfloat162float(h));
}

__global__ __launch_bounds__(256)
void prep_w(const float* __restrict__ W)
{
    const int o = blockIdx.z;
    const int i0 = blockIdx.y * 32, j0 = blockIdx.x * 32;
    __shared__ float t[32][33];
    const int tx = threadIdx.x & 31, ty = threadIdx.x >> 5;
    const float* Wo = W + (size_t)o * WSTRIDE;
    #pragma unroll
    for (int k = 0; k < 4; k++)
        t[ty + 8 * k][tx] = Wo[(size_t)(i0 + ty + 8 * k) * 513 + (j0 + tx)];
    __syncthreads();
    const size_t ob = (size_t)o * D * D;
    #pragma unroll
    for (int k = 0; k < 4; k++) {
        const int j = j0 + ty + 8 * k;
        float v = t[tx][ty + 8 * k];
        __nv_bfloat16 h = __float2bfloat16(v);
        g_Whi[ob + (size_t)j * D + i0 + tx] = h;
        g_Wlo[ob + (size_t)j * D + i0 + tx] = __float2bfloat16(v - __bfloat162float(h));
    }
}

__global__ __launch_bounds__(256)
void gather_w(const float* __restrict__ W)
{
    int idx = blockIdx.x * 256 + threadIdx.x;
    if (idx >= D * O) return;
    int d = idx >> 7, o = idx & 127;
    g_colWt[idx] = W[(size_t)o * WSTRIDE + (size_t)d * 513 + 512];
    g_rowWt[idx] = W[(size_t)o * WSTRIDE + (size_t)512 * 513 + d];
}

__global__ __launch_bounds__(128)
void lin_terms(const float* __restrict__ x1, const float* __restrict__ x2,
               const float* __restrict__ W, const float* __restrict__ Wlin,
               const float* __restrict__ b_lin, const float* __restrict__ bw)
{
    const int which = blockIdx.y;
    const int mg = blockIdx.x * 8;
    const int o = threadIdx.x;

    __shared__ float xs[8][D];
    const float* xsrc = which ? x2 : x1;
    for (int idx = o; idx < 8 * D; idx += 128)
        xs[idx >> 9][idx & 511] = xsrc[(size_t)mg * D + idx];
    __syncthreads();

    const float* wl0 = Wlin + (which ? (size_t)D * O : 0);
    const float* wb0 = which ? g_rowWt : g_colWt;

    float accl[8] = {}, accb[8] = {};
    for (int d = 0; d < D; d++) {
        const float wl = wl0[(size_t)d * O + o];
        const float wb = wb0[d * O + o];
        #pragma unroll
        for (int r = 0; r < 8; r++) {
            accl[r] = fmaf(xs[r][d], wl, accl[r]);
            accb[r] = fmaf(xs[r][d], wb, accb[r]);
        }
    }
    const float e0 = expf(bw[0]), e1 = expf(bw[1]);
    const float w0 = e0 / (e0 + e1), w1 = e1 / (e0 + e1);

    if (which == 0) {
        #pragma unroll
        for (int r = 0; r < 8; r++)
            g_A1[(size_t)(mg + r) * O + o] = w0 * accb[r] + w1 * (accl[r] + b_lin[o]);
    } else {
        const float corner = W[(size_t)o * WSTRIDE + (size_t)512 * 513 + 512];
        #pragma unroll
        for (int r = 0; r < 8; r++)
            g_A2[(size_t)(mg + r) * O + o] = w0 * (accb[r] + corner) + w1 * accl[r];
    }
}

// ---------------- stage 1: T[m, o, j] = x1[m,:] . Wt[o][j][:] ----------------
// grid (8 m-tiles, 512 (o,jtile)); x fastest so 8 CTAs share each W slab in L2.
__global__ __launch_bounds__(256, 1)
void stage1_mma()
{
    extern __shared__ char smem[];
    const uint32_t sb = s2u(smem);
    const int tid = threadIdx.x;
    const int m0 = blockIdx.x * 128;
    const int o  = blockIdx.y >> 2;
    const int j0 = (blockIdx.y & 3) * 128;

    float acc[4][4][4] = {};
    gemm_loop(sb, tid,
              g_x1hi + (size_t)m0 * D, g_x1lo + (size_t)m0 * D,
              g_Whi + (size_t)o * D * D + (size_t)j0 * D,
              g_Wlo + (size_t)o * D * D + (size_t)j0 * D, acc);

    const int lane = tid & 31;
    const int warp_m = (tid >> 5) & 1, warp_n = tid >> 6;
    #pragma unroll
    for (int mt = 0; mt < 4; mt++) {
        #pragma unroll
        for (int nt = 0; nt < 4; nt++) {
            const int m = m0 + warp_m * 64 + mt * 16 + (lane >> 2);
            const int j = j0 + warp_n * 32 + nt * 8 + (lane & 3) * 2;
            #pragma unroll
            for (int h = 0; h < 2; h++) {
                const float v0 = acc[mt][nt][h * 2], v1 = acc[mt][nt][h * 2 + 1];
                const size_t off = ((size_t)(m + h * 8) * O + o) * D + j;
                const __nv_bfloat16 h0 = __float2bfloat16(v0), h1 = __float2bfloat16(v1);
                *reinterpret_cast<__nv_bfloat162*>(g_Thi + off) = __nv_bfloat162(h0, h1);
                *reinterpret_cast<__nv_bfloat162*>(g_Tlo + off) = __nv_bfloat162(
                    __float2bfloat16(v0 - __bfloat162float(h0)),
                    __float2bfloat16(v1 - __bfloat162float(h1)));
            }
        }
    }
}

// ---------------- stage 2: out[bx, y, o] = w0 * x2[y,:] . T[bx][o][:] + A1 + A2
// grid (2 y-tiles, 1024 bx); 2 CTAs share each T slab.
__global__ __launch_bounds__(256, 1)
void stage2_mma(const float* __restrict__ bw, float* __restrict__ out)
{
    extern __shared__ char smem[];
    const uint32_t sb = s2u(smem);
    const int tid = threadIdx.x;
    const int y0 = blockIdx.x * 128;
    const int bx = blockIdx.y;
    const int b  = bx >> 8;
    const size_t arow = (size_t)(b * L + y0) * D;

    float acc[4][4][4] = {};
    gemm_loop(sb, tid,
              g_x2hi + arow, g_x2lo + arow,
              g_Thi + (size_t)bx * O * D, g_Tlo + (size_t)bx * O * D, acc);

    const float e0 = expf(bw[0]), e1 = expf(bw[1]);
    const float w0 = e0 / (e0 + e1);

    const int lane = tid & 31;
    const int warp_m = (tid >> 5) & 1, warp_n = tid >> 6;
    #pragma unroll
    for (int mt = 0; mt < 4; mt++) {
        #pragma unroll
        for (int nt = 0; nt < 4; nt++) {
            const int y  = y0 + warp_m * 64 + mt * 16 + (lane >> 2);
            const int oc = warp_n * 32 + nt * 8 + (lane & 3) * 2;
            const float a10 = g_A1[bx * O + oc], a11 = g_A1[bx * O + oc + 1];
            #pragma unroll
            for (int h = 0; h < 2; h++) {
                const int yy = y + h * 8;
                const size_t a2o = (size_t)(b * L + yy) * O + oc;
                float2 r;
                r.x = fmaf(w0, acc[mt][nt][h * 2],     a10 + g_A2[a2o]);
                r.y = fmaf(w0, acc[mt][nt][h * 2 + 1], a11 + g_A2[a2o + 1]);
                *reinterpret_cast<float2*>(out + ((size_t)bx * L + yy) * O + oc) = r;
            }
        }
    }
}

// ---------------------------------------------------------------------------
extern "C" void kernel_launch(void* const* d_in, const int* in_sizes, int n_in,
                              void* d_out, int out_size)
{
    const float* x1    = (const float*)d_in[0];
    const float* x2    = (const float*)d_in[1];
    const float* bw    = (const float*)d_in[2];
    const float* W_bil = (const float*)d_in[3];
    const float* W_lin = (const float*)d_in[4];
    const float* b_lin = (const float*)d_in[5];
    float* out = (float*)d_out;

    cudaFuncSetAttribute(stage1_mma, cudaFuncAttributeMaxDynamicSharedMemorySize, GSMEM);
    cudaFuncSetAttribute(stage2_mma, cudaFuncAttributeMaxDynamicSharedMemorySize, GSMEM);

    prep_x<<<(BX * D + 255) / 256, 256>>>(x1, x2);
    prep_w<<<dim3(16, 16, O), 256>>>(W_bil);
    gather_w<<<(D * O + 255) / 256, 256>>>(W_bil);
    lin_terms<<<dim3(BX / 8, 2), 128>>>(x1, x2, W_bil, W_lin, b_lin, bw);

    stage1_mma<<<dim3(8, 512), 256, GSMEM>>>();
    stage2_mma<<<dim3(2, BX), 256, GSMEM>>>(bw, out);
}

// round 6
// speedup vs baseline: 4.0704x; 1.3139x over previous
#include <cuda_runtime.h>
#include <cuda_bf16.h>
#include <cstdint>
#include <cstddef>
#include <math.h>

#define B 4
#define L 256
#define D 512
#define O 128
#define BX 1024
#define WSTRIDE 263169       // 513*513

// ---------------- device scratch (static, no runtime alloc) ----------------
__device__ __nv_bfloat16 g_x1hi[BX * D];
__device__ __nv_bfloat16 g_x1lo[BX * D];
__device__ __nv_bfloat16 g_x2hi[BX * D];
__device__ __nv_bfloat16 g_x2lo[BX * D];
__device__ __nv_bfloat16 g_Whi[(size_t)O * D * D];   // Wt[o][j][i]
__device__ __nv_bfloat16 g_Wlo[(size_t)O * D * D];
__device__ __nv_bfloat16 g_Thi[(size_t)BX * O * D];  // T[bx][o][j]
__device__ __nv_bfloat16 g_Tlo[(size_t)BX * O * D];
__device__ float g_Wc[2 * D * O];  // combined weights [which][d][o]
__device__ float g_bias[2 * O];    // [0]: w1*b_lin, [1]: w0*corner
__device__ float g_A1[BX * O];
__device__ float g_A2[BX * O];

// ---------------- low-level helpers ----------------
__device__ __forceinline__ uint32_t s2u(const void* p) {
    uint32_t a;
    asm("{ .reg .u64 t; cvta.to.shared.u64 t, %1; cvt.u32.u64 %0, t; }" : "=r"(a) : "l"(p));
    return a;
}
__device__ __forceinline__ void cpa16(uint32_t d, const void* s) {
    asm volatile("cp.async.cg.shared.global [%0], [%1], 16;" :: "r"(d), "l"(s) : "memory");
}
#define CP_COMMIT() asm volatile("cp.async.commit_group;" ::: "memory")

__device__ __forceinline__ void ldsm_x4(uint32_t a, uint32_t r[4]) {
    asm volatile("ldmatrix.sync.aligned.m8n8.x4.shared.b16 {%0,%1,%2,%3}, [%4];"
                 : "=r"(r[0]), "=r"(r[1]), "=r"(r[2]), "=r"(r[3]) : "r"(a));
}
__device__ __forceinline__ void mma16816(float c[4], const uint32_t a[4], const uint32_t b[2]) {
    asm volatile(
        "mma.sync.aligned.m16n8k16.row.col.f32.bf16.bf16.f32 "
        "{%0,%1,%2,%3}, {%4,%5,%6,%7}, {%8,%9}, {%0,%1,%2,%3};"
        : "+f"(c[0]), "+f"(c[1]), "+f"(c[2]), "+f"(c[3])
        : "r"(a[0]), "r"(a[1]), "r"(a[2]), "r"(a[3]), "r"(b[0]), "r"(b[1]));
}

// Tile geometry: 128 rows x 32 bf16 (64B) per k-chunk, 80B row stride.
#define TILE_B   10240      // 128 * 80
#define BUF_B    40960      // 4 tiles (Ah, Al, Bh, Bl)
#define GSMEM    81920      // 2 buffers

__device__ __forceinline__ void load_tile80(uint32_t dst, const __nv_bfloat16* src,
                                            int tid, int k0) {
    #pragma unroll
    for (int it = 0; it < 2; it++) {
        int op = it * 256 + tid;
        int row = op >> 2, ch = op & 3;
        cpa16(dst + row * 80 + ch * 16,
              (const char*)src + (size_t)row * 1024 + (size_t)k0 * 2 + ch * 16);
    }
}

__device__ __forceinline__ void compute_k16(uint32_t base, int kk, int lane,
                                            int warp_m, int warp_n, float acc[4][4][4]) {
    uint32_t ah[4][4], al[4][4];
    #pragma unroll
    for (int mt = 0; mt < 4; mt++) {
        int row = warp_m * 64 + mt * 16 + (lane & 7) + ((lane >> 3) & 1) * 8;
        int col = kk + (lane >> 4) * 8;
        uint32_t ad = base + row * 80 + col * 2;
        ldsm_x4(ad, ah[mt]);
        ldsm_x4(ad + TILE_B, al[mt]);
    }
    uint32_t bh[2][4], bl[2][4];
    #pragma unroll
    for (int p = 0; p < 2; p++) {
        int n = warp_n * 32 + p * 16 + (lane & 7) + (lane >> 4) * 8;
        int col = kk + ((lane >> 3) & 1) * 8;
        uint32_t bd = base + 2 * TILE_B + n * 80 + col * 2;
        ldsm_x4(bd, bh[p]);
        ldsm_x4(bd + TILE_B, bl[p]);
    }
    #pragma unroll
    for (int mt = 0; mt < 4; mt++)
        #pragma unroll
        for (int nt = 0; nt < 4; nt++) {
            const uint32_t* bhf = &bh[nt >> 1][(nt & 1) * 2];
            const uint32_t* blf = &bl[nt >> 1][(nt & 1) * 2];
            mma16816(acc[mt][nt], ah[mt], bhf);
            mma16816(acc[mt][nt], ah[mt], blf);
            mma16816(acc[mt][nt], al[mt], bhf);
        }
}

__device__ __forceinline__ void gemm_loop(uint32_t sb, int tid,
    const __nv_bfloat16* Ah, const __nv_bfloat16* Al,
    const __nv_bfloat16* Bh, const __nv_bfloat16* Bl,
    float acc[4][4][4])
{
    const int lane = tid & 31;
    const int warp_m = (tid >> 5) & 1, warp_n = tid >> 6;

    load_tile80(sb,               Ah, tid, 0);
    load_tile80(sb + TILE_B,      Al, tid, 0);
    load_tile80(sb + 2 * TILE_B,  Bh, tid, 0);
    load_tile80(sb + 3 * TILE_B,  Bl, tid, 0);
    CP_COMMIT();

    #pragma unroll 1
    for (int c = 0; c < 16; c++) {
        if (c + 1 < 16) {
            const uint32_t nb = sb + ((c + 1) & 1) * BUF_B;
            const int k0 = (c + 1) * 32;
            load_tile80(nb,              Ah, tid, k0);
            load_tile80(nb + TILE_B,     Al, tid, k0);
            load_tile80(nb + 2 * TILE_B, Bh, tid, k0);
            load_tile80(nb + 3 * TILE_B, Bl, tid, k0);
            CP_COMMIT();
            asm volatile("cp.async.wait_group 1;" ::: "memory");
        } else {
            asm volatile("cp.async.wait_group 0;" ::: "memory");
        }
        __syncthreads();
        const uint32_t base = sb + (c & 1) * BUF_B;
        compute_k16(base, 0,  lane, warp_m, warp_n, acc);
        compute_k16(base, 16, lane, warp_m, warp_n, acc);
        __syncthreads();
    }
}

// ---------------- pre-pass kernels ----------------
__global__ __launch_bounds__(256)
void prep_x(const float* __restrict__ x1, const float* __restrict__ x2)
{
    int i = blockIdx.x * 256 + threadIdx.x;
    if (i >= BX * D) return;
    float v = x1[i];
    __nv_bfloat16 h = __float2bfloat16(v);
    g_x1hi[i] = h; g_x1lo[i] = __float2bfloat16(v - __bfloat162float(h));
    v = x2[i];
    h = __float2bfloat16(v);
    g_x2hi[i] = h; g_x2lo[i] = __float2bfloat16(v - __bfloat162float(h));
}

// Transpose + split W core: Wt[o][j][i]. 64(i) x 32(j) tiles; bf16x2 stores.
__global__ __launch_bounds__(256)
void prep_w(const float* __restrict__ W)
{
    const int o  = blockIdx.z;
    const int i0 = blockIdx.y * 64, j0 = blockIdx.x * 32;
    __shared__ float t[64][33];
    const int tid = threadIdx.x;
    const float* Wo = W + (size_t)o * WSTRIDE;

    #pragma unroll
    for (int p = 0; p < 8; p++) {
        int idx = p * 256 + tid;
        int i = idx >> 5, j = idx & 31;
        t[i][j] = Wo[(size_t)(i0 + i) * 513 + (j0 + j)];
    }
    __syncthreads();

    const size_t ob = (size_t)o * D * D;
    #pragma unroll
    for (int p = 0; p < 4; p++) {
        const int j  = j0 + p * 8 + (tid >> 5);
        const int i2 = (tid & 31) * 2;
        float v0 = t[i2][j - j0 + 0 * 0 + (p * 8 + (tid >> 5))] ; // placeholder avoided below
        // direct indexing (smem tile is [i][j-local]):
        v0 = t[i2][p * 8 + (tid >> 5)];
        float v1 = t[i2 + 1][p * 8 + (tid >> 5)];
        __nv_bfloat16 h0 = __float2bfloat16(v0), h1 = __float2bfloat16(v1);
        __nv_bfloat16 l0 = __float2bfloat16(v0 - __bfloat162float(h0));
        __nv_bfloat16 l1 = __float2bfloat16(v1 - __bfloat162float(h1));
        const size_t off = ob + (size_t)j * D + i0 + i2;
        *reinterpret_cast<__nv_bfloat162*>(g_Whi + off) = __nv_bfloat162(h0, h1);
        *reinterpret_cast<__nv_bfloat162*>(g_Wlo + off) = __nv_bfloat162(l0, l1);
    }
}

// Combined weights: Wc[0][d][o] = w0*W[o][d][512] + w1*Wlin[d][o]
//                   Wc[1][d][o] = w0*W[o][512][d] + w1*Wlin[D+d][o]
__global__ __launch_bounds__(256)
void comb_w(const float* __restrict__ W, const float* __restrict__ Wlin,
            const float* __restrict__ b_lin, const float* __restrict__ bw)
{
    const int idx = blockIdx.x * 256 + threadIdx.x;   // over 2*D*O
    if (idx >= 2 * D * O) return;
    const float e0 = expf(bw[0]), e1 = expf(bw[1]);
    const float w0 = e0 / (e0 + e1), w1 = e1 / (e0 + e1);

    const int which = idx >= D * O;
    const int r = idx - which * D * O;
    const int d = r >> 7, o = r & 127;
    const float we = which ? W[(size_t)o * WSTRIDE + (size_t)512 * 513 + d]
                           : W[(size_t)o * WSTRIDE + (size_t)d * 513 + 512];
    const float wl = Wlin[(size_t)(which * D + d) * O + o];
    g_Wc[idx] = w0 * we + w1 * wl;

    if (idx < O)           g_bias[idx] = w1 * b_lin[idx];
    else if (idx < 2 * O) {
        const int oo = idx - O;
        g_bias[idx] = w0 * W[(size_t)oo * WSTRIDE + (size_t)512 * 513 + 512];
    }
}

// A1/A2 = x @ Wc + bias. grid (128 m-tiles of 8 rows, 2 which), 256 threads.
__global__ __launch_bounds__(256)
void A_terms(const float* __restrict__ x1, const float* __restrict__ x2)
{
    const int which = blockIdx.y;
    const int mg = blockIdx.x * 8;
    const int tid = threadIdx.x;
    const int o = tid & 127, half = tid >> 7;

    __shared__ float xs[8][D];
    const float* xsrc = (which ? x2 : x1) + (size_t)mg * D;
    #pragma unroll
    for (int p = 0; p < 4; p++)
        reinterpret_cast<float4*>(&xs[0][0])[p * 256 + tid] =
            reinterpret_cast<const float4*>(xsrc)[p * 256 + tid];
    __syncthreads();

    const float* wc = g_Wc + which * D * O;
    float acc[4] = {};
    #pragma unroll 4
    for (int d = 0; d < D; d++) {
        const float w = wc[d * O + o];
        #pragma unroll
        for (int r = 0; r < 4; r++)
            acc[r] = fmaf(xs[half * 4 + r][d], w, acc[r]);
    }
    const float bias = g_bias[which * O + o];
    float* dst = which ? g_A2 : g_A1;
    #pragma unroll
    for (int r = 0; r < 4; r++)
        dst[(size_t)(mg + half * 4 + r) * O + o] = acc[r] + bias;
}

// ---------------- stage 1: T[m, o, j] = x1[m,:] . Wt[o][j][:] ----------------
#define S1_PITCH 272        // 136 bf16 per staged row
__global__ __launch_bounds__(256, 2)
void stage1_mma()
{
    extern __shared__ char smem[];
    const uint32_t sb = s2u(smem);
    const int tid = threadIdx.x;
    const int m0 = blockIdx.x * 128;
    const int o  = blockIdx.y >> 2;
    const int j0 = (blockIdx.y & 3) * 128;

    float acc[4][4][4] = {};
    gemm_loop(sb, tid,
              g_x1hi + (size_t)m0 * D, g_x1lo + (size_t)m0 * D,
              g_Whi + (size_t)o * D * D + (size_t)j0 * D,
              g_Wlo + (size_t)o * D * D + (size_t)j0 * D, acc);

    // smem-staged epilogue: hi plane at 0, lo plane at 128*272
    const int lane = tid & 31;
    const int warp_m = (tid >> 5) & 1, warp_n = tid >> 6;
    #pragma unroll
    for (int mt = 0; mt < 4; mt++)
        #pragma unroll
        for (int nt = 0; nt < 4; nt++)
            #pragma unroll
            for (int h = 0; h < 2; h++) {
                const int ml = warp_m * 64 + mt * 16 + (lane >> 2) + h * 8;
                const int jl = warp_n * 32 + nt * 8 + (lane & 3) * 2;
                const float v0 = acc[mt][nt][h * 2], v1 = acc[mt][nt][h * 2 + 1];
                const __nv_bfloat16 h0 = __float2bfloat16(v0), h1 = __float2bfloat16(v1);
                *reinterpret_cast<__nv_bfloat162*>(smem + ml * S1_PITCH + jl * 2) =
                    __nv_bfloat162(h0, h1);
                *reinterpret_cast<__nv_bfloat162*>(smem + 128 * S1_PITCH + ml * S1_PITCH + jl * 2) =
                    __nv_bfloat162(__float2bfloat16(v0 - __bfloat162float(h0)),
                                   __float2bfloat16(v1 - __bfloat162float(h1)));
            }
    __syncthreads();

    // coalesced copy-out: 128 rows x 256B per plane
    #pragma unroll
    for (int p = 0; p < 8; p++) {
        const int q = p * 256 + tid;
        const int r = q >> 4, c = q & 15;
        const size_t go = ((size_t)(m0 + r) * O + o) * D + j0 + c * 8;
        *reinterpret_cast<uint4*>(g_Thi + go) =
            *reinterpret_cast<uint4*>(smem + r * S1_PITCH + c * 16);
        *reinterpret_cast<uint4*>(g_Tlo + go) =
            *reinterpret_cast<uint4*>(smem + 128 * S1_PITCH + r * S1_PITCH + c * 16);
    }
}

// ---------------- stage 2: out = w0 * x2 . T[bx] + A1 + A2 ----------------
#define S2_PITCH 528        // 132 floats per staged row
__global__ __launch_bounds__(256, 2)
void stage2_mma(const float* __restrict__ bw, float* __restrict__ out)
{
    extern __shared__ char smem[];
    const uint32_t sb = s2u(smem);
    const int tid = threadIdx.x;
    const int y0 = blockIdx.x * 128;
    const int bx = blockIdx.y;
    const int b  = bx >> 8;
    const size_t arow = (size_t)(b * L + y0) * D;

    float acc[4][4][4] = {};
    gemm_loop(sb, tid,
              g_x2hi + arow, g_x2lo + arow,
              g_Thi + (size_t)bx * O * D, g_Tlo + (size_t)bx * O * D, acc);

    // stage C (fp32) to smem
    const int lane = tid & 31;
    const int warp_m = (tid >> 5) & 1, warp_n = tid >> 6;
    #pragma unroll
    for (int mt = 0; mt < 4; mt++)
        #pragma unroll
        for (int nt = 0; nt < 4; nt++)
            #pragma unroll
            for (int h = 0; h < 2; h++) {
                const int yl = warp_m * 64 + mt * 16 + (lane >> 2) + h * 8;
                const int ol = warp_n * 32 + nt * 8 + (lane & 3) * 2;
                *reinterpret_cast<float2*>(smem + yl * S2_PITCH + ol * 4) =
                    make_float2(acc[mt][nt][h * 2], acc[mt][nt][h * 2 + 1]);
            }
    __syncthreads();

    const float e0 = expf(bw[0]), e1 = expf(bw[1]);
    const float w0 = e0 / (e0 + e1);

    // fused copy-out: out = w0*C + A1[o] + A2[y][o], 512B rows
    #pragma unroll
    for (int p = 0; p < 16; p++) {
        const int q = p * 256 + tid;
        const int r = q >> 5, c = q & 31;          // row, float4-col
        const float4 v = *reinterpret_cast<float4*>(smem + r * S2_PITCH + c * 16);
        const float4 a1 = *reinterpret_cast<const float4*>(g_A1 + (size_t)bx * O + c * 4);
        const float4 a2 = *reinterpret_cast<const float4*>(g_A2 + (size_t)(b * L + y0 + r) * O + c * 4);
        float4 rr;
        rr.x = fmaf(w0, v.x, a1.x + a2.x);
        rr.y = fmaf(w0, v.y, a1.y + a2.y);
        rr.z = fmaf(w0, v.z, a1.z + a2.z);
        rr.w = fmaf(w0, v.w, a1.w + a2.w);
        *reinterpret_cast<float4*>(out + ((size_t)bx * L + y0 + r) * O + c * 4) = rr;
    }
}

// ---------------------------------------------------------------------------
extern "C" void kernel_launch(void* const* d_in, const int* in_sizes, int n_in,
                              void* d_out, int out_size)
{
    const float* x1    = (const float*)d_in[0];
    const float* x2    = (const float*)d_in[1];
    const float* bw    = (const float*)d_in[2];
    const float* W_bil = (const float*)d_in[3];
    const float* W_lin = (const float*)d_in[4];
    const float* b_lin = (const float*)d_in[5];
    float* out = (float*)d_out;

    cudaFuncSetAttribute(stage1_mma, cudaFuncAttributeMaxDynamicSharedMemorySize, GSMEM);
    cudaFuncSetAttribute(stage2_mma, cudaFuncAttributeMaxDynamicSharedMemorySize, GSMEM);

    prep_x<<<(BX * D + 255) / 256, 256>>>(x1, x2);
    prep_w<<<dim3(16, 8, O), 256>>>(W_bil);
    comb_w<<<(2 * D * O + 255) / 256, 256>>>(W_bil, W_lin, b_lin, bw);
    A_terms<<<dim3(BX / 8, 2), 256>>>(x1, x2);

    stage1_mma<<<dim3(8, 512), 256, GSMEM>>>();
    stage2_mma<<<dim3(2, BX), 256, GSMEM>>>(bw, out);
}

// round 7
// speedup vs baseline: 4.8129x; 1.1824x over previous
#include <cuda_runtime.h>
#include <cuda_bf16.h>
#include <cstdint>
#include <cstddef>
#include <math.h>

#define B 4
#define L 256
#define D 512
#define O 128
#define BX 1024
#define WSTRIDE 263169       // 513*513

// ---------------- device scratch (static, no runtime alloc) ----------------
__device__ __nv_bfloat16 g_x1hi[BX * D];
__device__ __nv_bfloat16 g_x1lo[BX * D];
__device__ __nv_bfloat16 g_x2hi[BX * D];
__device__ __nv_bfloat16 g_x2lo[BX * D];
__device__ __nv_bfloat16 g_Whi[(size_t)O * D * D];   // Wt[o][j][i]
__device__ __nv_bfloat16 g_Wlo[(size_t)O * D * D];
__device__ __nv_bfloat16 g_Thi[(size_t)BX * O * D];  // T[bx][o][j]
__device__ __nv_bfloat16 g_Tlo[(size_t)BX * O * D];
__device__ __nv_bfloat16 g_WcHi[2 * O * D];  // [which][o][d] K-major
__device__ __nv_bfloat16 g_WcLo[2 * O * D];
__device__ float g_bias[2 * O];    // [0][o]: w1*b_lin, [1][o]: w0*corner
__device__ float g_A1[BX * O];
__device__ float g_A2[BX * O];

// ---------------- low-level helpers ----------------
__device__ __forceinline__ uint32_t s2u(const void* p) {
    uint32_t a;
    asm("{ .reg .u64 t; cvta.to.shared.u64 t, %1; cvt.u32.u64 %0, t; }" : "=r"(a) : "l"(p));
    return a;
}
__device__ __forceinline__ void cpa16(uint32_t d, const void* s) {
    asm volatile("cp.async.cg.shared.global [%0], [%1], 16;" :: "r"(d), "l"(s) : "memory");
}
#define CP_COMMIT() asm volatile("cp.async.commit_group;" ::: "memory")

__device__ __forceinline__ void ldsm_x4(uint32_t a, uint32_t r[4]) {
    asm volatile("ldmatrix.sync.aligned.m8n8.x4.shared.b16 {%0,%1,%2,%3}, [%4];"
                 : "=r"(r[0]), "=r"(r[1]), "=r"(r[2]), "=r"(r[3]) : "r"(a));
}
__device__ __forceinline__ void mma16816(float c[4], const uint32_t a[4], const uint32_t b[2]) {
    asm volatile(
        "mma.sync.aligned.m16n8k16.row.col.f32.bf16.bf16.f32 "
        "{%0,%1,%2,%3}, {%4,%5,%6,%7}, {%8,%9}, {%0,%1,%2,%3};"
        : "+f"(c[0]), "+f"(c[1]), "+f"(c[2]), "+f"(c[3])
        : "r"(a[0]), "r"(a[1]), "r"(a[2]), "r"(a[3]), "r"(b[0]), "r"(b[1]));
}

// ---- packed tiles: 128 rows x 128B (hi bf16 cols 0..31 -> bytes 0..63, lo -> 64..127)
// SW128 swizzle: column-16B-chunk XORed with row&7.
#define TILE16K  16384
#define STAGE_B  32768      // A tile + B tile
#define NSTAGE   3
#define GSMEM    98304      // 3 stages

__device__ __forceinline__ uint32_t swa(uint32_t base, int row, int colb) {
    return base + row * 128 + (colb ^ ((row & 7) << 4));
}

// cooperatively load one stage: A(hi|lo) + B(hi|lo), BK=32, gmem row stride 512 elems
__device__ __forceinline__ void load_stage(uint32_t sb, int s,
    const __nv_bfloat16* Ah, const __nv_bfloat16* Al,
    const __nv_bfloat16* Bh, const __nv_bfloat16* Bl,
    int tid, int k0)
{
    const __nv_bfloat16* srcs[4] = {Ah, Al, Bh, Bl};
    const uint32_t st = sb + s * STAGE_B;
    #pragma unroll
    for (int it = 0; it < 8; it++) {
        const int op = it * 256 + tid;          // 0..2047
        const int tile = op >> 10;              // 0=A, 1=B
        const int rem = op & 1023;
        const int r = rem >> 3, sub = rem & 7;
        const int p = sub >> 2, ch = sub & 3;   // plane, 16B chunk
        const uint32_t dst = swa(st + tile * TILE16K, r, p * 64 + ch * 16);
        const char* src = (const char*)srcs[tile * 2 + p]
                        + (size_t)r * 1024 + (size_t)k0 * 2 + ch * 16;
        cpa16(dst, src);
    }
}

__device__ __forceinline__ void compute_k16(uint32_t base, int kk, int lane,
                                            int warp_m, int warp_n, float acc[4][4][4]) {
    uint32_t ah[4][4], al[4][4];
    const int cola = kk * 2 + (lane >> 4) * 16;
    #pragma unroll
    for (int mt = 0; mt < 4; mt++) {
        const int row = warp_m * 64 + mt * 16 + (lane & 7) + ((lane >> 3) & 1) * 8;
        ldsm_x4(swa(base, row, cola), ah[mt]);
        ldsm_x4(swa(base, row, 64 + cola), al[mt]);
    }
    uint32_t bh[2][4], bl[2][4];
    const int colb = kk * 2 + ((lane >> 3) & 1) * 16;
    #pragma unroll
    for (int p = 0; p < 2; p++) {
        const int n = warp_n * 32 + p * 16 + (lane & 7) + (lane >> 4) * 8;
        ldsm_x4(swa(base + TILE16K, n, colb), bh[p]);
        ldsm_x4(swa(base + TILE16K, n, 64 + colb), bl[p]);
    }
    #pragma unroll
    for (int mt = 0; mt < 4; mt++)
        #pragma unroll
        for (int nt = 0; nt < 4; nt++) {
            const uint32_t* bhf = &bh[nt >> 1][(nt & 1) * 2];
            const uint32_t* blf = &bl[nt >> 1][(nt & 1) * 2];
            mma16816(acc[mt][nt], ah[mt], bhf);
            mma16816(acc[mt][nt], ah[mt], blf);
            mma16816(acc[mt][nt], al[mt], bhf);
        }
}

// C[128x128] += Ah*Bh^T + Ah*Bl^T + Al*Bh^T over K=512; 3-stage, 1 sync/chunk
__device__ __forceinline__ void gemm_loop(uint32_t sb, int tid,
    const __nv_bfloat16* Ah, const __nv_bfloat16* Al,
    const __nv_bfloat16* Bh, const __nv_bfloat16* Bl,
    float acc[4][4][4])
{
    const int lane = tid & 31;
    const int warp_m = (tid >> 5) & 1, warp_n = tid >> 6;

    load_stage(sb, 0, Ah, Al, Bh, Bl, tid, 0);  CP_COMMIT();
    load_stage(sb, 1, Ah, Al, Bh, Bl, tid, 32); CP_COMMIT();

    #pragma unroll 1
    for (int c = 0; c < 16; c++) {
        if (c + 1 < 16) asm volatile("cp.async.wait_group 1;" ::: "memory");
        else            asm volatile("cp.async.wait_group 0;" ::: "memory");
        __syncthreads();
        if (c + 2 < 16) {
            load_stage(sb, (c + 2) % NSTAGE, Ah, Al, Bh, Bl, tid, (c + 2) * 32);
            CP_COMMIT();
        }
        const uint32_t base = sb + (c % NSTAGE) * STAGE_B;
        compute_k16(base, 0,  lane, warp_m, warp_n, acc);
        compute_k16(base, 16, lane, warp_m, warp_n, acc);
    }
    __syncthreads();   // protect smem reuse by epilogues
}

// ---------------- pre-pass kernels ----------------
__global__ __launch_bounds__(256)
void prep_x(const float* __restrict__ x1, const float* __restrict__ x2)
{
    int i = blockIdx.x * 256 + threadIdx.x;
    if (i >= BX * D) return;
    float v = x1[i];
    __nv_bfloat16 h = __float2bfloat16(v);
    g_x1hi[i] = h; g_x1lo[i] = __float2bfloat16(v - __bfloat162float(h));
    v = x2[i];
    h = __float2bfloat16(v);
    g_x2hi[i] = h; g_x2lo[i] = __float2bfloat16(v - __bfloat162float(h));
}

// Transpose + split W core: Wt[o][j][i]
__global__ __launch_bounds__(256)
void prep_w(const float* __restrict__ W)
{
    const int o  = blockIdx.z;
    const int i0 = blockIdx.y * 64, j0 = blockIdx.x * 32;
    __shared__ float t[64][33];
    const int tid = threadIdx.x;
    const float* Wo = W + (size_t)o * WSTRIDE;

    #pragma unroll
    for (int p = 0; p < 8; p++) {
        int idx = p * 256 + tid;
        int i = idx >> 5, j = idx & 31;
        t[i][j] = Wo[(size_t)(i0 + i) * 513 + (j0 + j)];
    }
    __syncthreads();

    const size_t ob = (size_t)o * D * D;
    #pragma unroll
    for (int p = 0; p < 4; p++) {
        const int jl = p * 8 + (tid >> 5);
        const int i2 = (tid & 31) * 2;
        const float v0 = t[i2][jl], v1 = t[i2 + 1][jl];
        const __nv_bfloat16 h0 = __float2bfloat16(v0), h1 = __float2bfloat16(v1);
        const size_t off = ob + (size_t)(j0 + jl) * D + i0 + i2;
        *reinterpret_cast<__nv_bfloat162*>(g_Whi + off) = __nv_bfloat162(h0, h1);
        *reinterpret_cast<__nv_bfloat162*>(g_Wlo + off) = __nv_bfloat162(
            __float2bfloat16(v0 - __bfloat162float(h0)),
            __float2bfloat16(v1 - __bfloat162float(h1)));
    }
}

// Combined weights, transposed + split:
//  Wc[0][o][d] = w0*W[o][d][512] + w1*Wlin[d][o]
//  Wc[1][o][d] = w0*W[o][512][d] + w1*Wlin[D+d][o]
__global__ __launch_bounds__(256)
void comb_w(const float* __restrict__ W, const float* __restrict__ Wlin,
            const float* __restrict__ b_lin, const float* __restrict__ bw)
{
    const int idx = blockIdx.x * 256 + threadIdx.x;   // over 2*O*D
    if (idx >= 2 * O * D) return;
    const float e0 = expf(bw[0]), e1 = expf(bw[1]);
    const float w0 = e0 / (e0 + e1), w1 = e1 / (e0 + e1);

    const int d = idx & 511;
    const int o = (idx >> 9) & 127;
    const int which = idx >> 16;
    const float we = which ? W[(size_t)o * WSTRIDE + (size_t)512 * 513 + d]
                           : W[(size_t)o * WSTRIDE + (size_t)d * 513 + 512];
    const float wl = Wlin[(size_t)(which * D + d) * O + o];
    const float v = w0 * we + w1 * wl;
    const __nv_bfloat16 h = __float2bfloat16(v);
    g_WcHi[idx] = h;
    g_WcLo[idx] = __float2bfloat16(v - __bfloat162float(h));

    if (idx < O)          g_bias[idx] = w1 * b_lin[idx];
    else if (idx < 2 * O) {
        const int oo = idx - O;
        g_bias[idx] = w0 * W[(size_t)oo * WSTRIDE + (size_t)512 * 513 + 512];
    }
}

// A-terms via tensor cores: A{1,2}[m, o] = x @ Wc[which]^T + bias
__global__ __launch_bounds__(256, 2)
void A_terms_mma()
{
    extern __shared__ char smem[];
    const uint32_t sb = s2u(smem);
    const int tid = threadIdx.x;
    const int m0 = blockIdx.x * 128;
    const int which = blockIdx.y;

    const __nv_bfloat16* Ah = (which ? g_x2hi : g_x1hi) + (size_t)m0 * D;
    const __nv_bfloat16* Al = (which ? g_x2lo : g_x1lo) + (size_t)m0 * D;
    const __nv_bfloat16* Bh = g_WcHi + (size_t)which * O * D;
    const __nv_bfloat16* Bl = g_WcLo + (size_t)which * O * D;

    float acc[4][4][4] = {};
    gemm_loop(sb, tid, Ah, Al, Bh, Bl, acc);

    float* dst = which ? g_A2 : g_A1;
    const float* bias = g_bias + which * O;
    const int lane = tid & 31;
    const int warp_m = (tid >> 5) & 1, warp_n = tid >> 6;
    #pragma unroll
    for (int mt = 0; mt < 4; mt++)
        #pragma unroll
        for (int nt = 0; nt < 4; nt++) {
            const int oc = warp_n * 32 + nt * 8 + (lane & 3) * 2;
            const float b0 = bias[oc], b1 = bias[oc + 1];
            #pragma unroll
            for (int h = 0; h < 2; h++) {
                const int m = m0 + warp_m * 64 + mt * 16 + (lane >> 2) + h * 8;
                *reinterpret_cast<float2*>(dst + (size_t)m * O + oc) =
                    make_float2(acc[mt][nt][h * 2] + b0, acc[mt][nt][h * 2 + 1] + b1);
            }
        }
}

// ---------------- stage 1: T[m, o, j] = x1[m,:] . Wt[o][j][:] ----------------
#define S1_PITCH 272
__global__ __launch_bounds__(256, 2)
void stage1_mma()
{
    extern __shared__ char smem[];
    const uint32_t sb = s2u(smem);
    const int tid = threadIdx.x;
    const int m0 = blockIdx.x * 128;
    const int o  = blockIdx.y >> 2;
    const int j0 = (blockIdx.y & 3) * 128;

    float acc[4][4][4] = {};
    gemm_loop(sb, tid,
              g_x1hi + (size_t)m0 * D, g_x1lo + (size_t)m0 * D,
              g_Whi + (size_t)o * D * D + (size_t)j0 * D,
              g_Wlo + (size_t)o * D * D + (size_t)j0 * D, acc);

    const int lane = tid & 31;
    const int warp_m = (tid >> 5) & 1, warp_n = tid >> 6;
    #pragma unroll
    for (int mt = 0; mt < 4; mt++)
        #pragma unroll
        for (int nt = 0; nt < 4; nt++)
            #pragma unroll
            for (int h = 0; h < 2; h++) {
                const int ml = warp_m * 64 + mt * 16 + (lane >> 2) + h * 8;
                const int jl = warp_n * 32 + nt * 8 + (lane & 3) * 2;
                const float v0 = acc[mt][nt][h * 2], v1 = acc[mt][nt][h * 2 + 1];
                const __nv_bfloat16 h0 = __float2bfloat16(v0), h1 = __float2bfloat16(v1);
                *reinterpret_cast<__nv_bfloat162*>(smem + ml * S1_PITCH + jl * 2) =
                    __nv_bfloat162(h0, h1);
                *reinterpret_cast<__nv_bfloat162*>(smem + 128 * S1_PITCH + ml * S1_PITCH + jl * 2) =
                    __nv_bfloat162(__float2bfloat16(v0 - __bfloat162float(h0)),
                                   __float2bfloat16(v1 - __bfloat162float(h1)));
            }
    __syncthreads();

    #pragma unroll
    for (int p = 0; p < 8; p++) {
        const int q = p * 256 + tid;
        const int r = q >> 4, c = q & 15;
        const size_t go = ((size_t)(m0 + r) * O + o) * D + j0 + c * 8;
        *reinterpret_cast<uint4*>(g_Thi + go) =
            *reinterpret_cast<uint4*>(smem + r * S1_PITCH + c * 16);
        *reinterpret_cast<uint4*>(g_Tlo + go) =
            *reinterpret_cast<uint4*>(smem + 128 * S1_PITCH + r * S1_PITCH + c * 16);
    }
}

// ---------------- stage 2: out = w0 * x2 . T[bx] + A1 + A2 ----------------
#define S2_PITCH 528
__global__ __launch_bounds__(256, 2)
void stage2_mma(const float* __restrict__ bw, float* __restrict__ out)
{
    extern __shared__ char smem[];
    const uint32_t sb = s2u(smem);
    const int tid = threadIdx.x;
    const int y0 = blockIdx.x * 128;
    const int bx = blockIdx.y;
    const int b  = bx >> 8;
    const size_t arow = (size_t)(b * L + y0) * D;

    float acc[4][4][4] = {};
    gemm_loop(sb, tid,
              g_x2hi + arow, g_x2lo + arow,
              g_Thi + (size_t)bx * O * D, g_Tlo + (size_t)bx * O * D, acc);

    const int lane = tid & 31;
    const int warp_m = (tid >> 5) & 1, warp_n = tid >> 6;
    #pragma unroll
    for (int mt = 0; mt < 4; mt++)
        #pragma unroll
        for (int nt = 0; nt < 4; nt++)
            #pragma unroll
            for (int h = 0; h < 2; h++) {
                const int yl = warp_m * 64 + mt * 16 + (lane >> 2) + h * 8;
                const int ol = warp_n * 32 + nt * 8 + (lane & 3) * 2;
                *reinterpret_cast<float2*>(smem + yl * S2_PITCH + ol * 4) =
                    make_float2(acc[mt][nt][h * 2], acc[mt][nt][h * 2 + 1]);
            }
    __syncthreads();

    const float e0 = expf(bw[0]), e1 = expf(bw[1]);
    const float w0 = e0 / (e0 + e1);

    #pragma unroll
    for (int p = 0; p < 16; p++) {
        const int q = p * 256 + tid;
        const int r = q >> 5, c = q & 31;
        const float4 v = *reinterpret_cast<float4*>(smem + r * S2_PITCH + c * 16);
        const float4 a1 = *reinterpret_cast<const float4*>(g_A1 + (size_t)bx * O + c * 4);
        const float4 a2 = *reinterpret_cast<const float4*>(g_A2 + (size_t)(b * L + y0 + r) * O + c * 4);
        float4 rr;
        rr.x = fmaf(w0, v.x, a1.x + a2.x);
        rr.y = fmaf(w0, v.y, a1.y + a2.y);
        rr.z = fmaf(w0, v.z, a1.z + a2.z);
        rr.w = fmaf(w0, v.w, a1.w + a2.w);
        *reinterpret_cast<float4*>(out + ((size_t)bx * L + y0 + r) * O + c * 4) = rr;
    }
}

// ---------------------------------------------------------------------------
extern "C" void kernel_launch(void* const* d_in, const int* in_sizes, int n_in,
                              void* d_out, int out_size)
{
    const float* x1    = (const float*)d_in[0];
    const float* x2    = (const float*)d_in[1];
    const float* bw    = (const float*)d_in[2];
    const float* W_bil = (const float*)d_in[3];
    const float* W_lin = (const float*)d_in[4];
    const float* b_lin = (const float*)d_in[5];
    float* out = (float*)d_out;

    cudaFuncSetAttribute(A_terms_mma, cudaFuncAttributeMaxDynamicSharedMemorySize, GSMEM);
    cudaFuncSetAttribute(stage1_mma,  cudaFuncAttributeMaxDynamicSharedMemorySize, GSMEM);
    cudaFuncSetAttribute(stage2_mma,  cudaFuncAttributeMaxDynamicSharedMemorySize, GSMEM);

    prep_x<<<(BX * D + 255) / 256, 256>>>(x1, x2);
    prep_w<<<dim3(16, 8, O), 256>>>(W_bil);
    comb_w<<<(2 * O * D + 255) / 256, 256>>>(W_bil, W_lin, b_lin, bw);
    A_terms_mma<<<dim3(8, 2), 256, GSMEM>>>();

    stage1_mma<<<dim3(8, 512), 256, GSMEM>>>();
    stage2_mma<<<dim3(2, BX), 256, GSMEM>>>(bw, out);
}

// round 8
// speedup vs baseline: 6.2857x; 1.3060x over previous
#include <cuda_runtime.h>
#include <cuda_fp16.h>
#include <cstdint>
#include <cstddef>
#include <math.h>

#define B 4
#define L 256
#define D 512
#define O 128
#define BX 1024
#define WSTRIDE 263169       // 513*513
#define WSCALE 256.0f
#define INV_WSCALE (1.0f/256.0f)

// ---------------- device scratch (static, no runtime alloc) ----------------
__device__ __half g_x1h[BX * D];
__device__ __half g_x2h[BX * D];
__device__ __half g_Wh[(size_t)O * D * D];   // 256*Wt[o][j][i], hi
__device__ __half g_Wl[(size_t)O * D * D];   // lo residual
__device__ __half g_Th[(size_t)BX * O * D];  // 256*T[bx][o][j], hi
__device__ __half g_Tl[(size_t)BX * O * D];
__device__ __half g_WcH[2 * O * D];          // 256*Wc[which][o][d]
__device__ __half g_WcL[2 * O * D];
__device__ float g_bias[2 * O];    // [0][o]: w1*b_lin, [1][o]: w0*corner
__device__ float g_A1[BX * O];
__device__ float g_A2[BX * O];

// ---------------- low-level helpers ----------------
__device__ __forceinline__ uint32_t s2u(const void* p) {
    uint32_t a;
    asm("{ .reg .u64 t; cvta.to.shared.u64 t, %1; cvt.u32.u64 %0, t; }" : "=r"(a) : "l"(p));
    return a;
}
__device__ __forceinline__ void cpa16(uint32_t d, const void* s) {
    asm volatile("cp.async.cg.shared.global [%0], [%1], 16;" :: "r"(d), "l"(s) : "memory");
}
#define CP_COMMIT() asm volatile("cp.async.commit_group;" ::: "memory")

__device__ __forceinline__ void ldsm_x4(uint32_t a, uint32_t r[4]) {
    asm volatile("ldmatrix.sync.aligned.m8n8.x4.shared.b16 {%0,%1,%2,%3}, [%4];"
                 : "=r"(r[0]), "=r"(r[1]), "=r"(r[2]), "=r"(r[3]) : "r"(a));
}
__device__ __forceinline__ void mma16816(float c[4], const uint32_t a[4], const uint32_t b[2]) {
    asm volatile(
        "mma.sync.aligned.m16n8k16.row.col.f32.f16.f16.f32 "
        "{%0,%1,%2,%3}, {%4,%5,%6,%7}, {%8,%9}, {%0,%1,%2,%3};"
        : "+f"(c[0]), "+f"(c[1]), "+f"(c[2]), "+f"(c[3])
        : "r"(a[0]), "r"(a[1]), "r"(a[2]), "r"(a[3]), "r"(b[0]), "r"(b[1]));
}

// ---- tiles per BK=32 chunk:
//  A: 128 rows x 32 fp16 (64B) + 16B pad -> 80B stride, no swizzle (banks verified)
//  B: 128 rows x 128B (hi 32 fp16 | lo 32 fp16), SW128-style XOR swizzle
#define A_TILE   10240      // 128*80
#define B_TILE   16384      // 128*128
#define STAGE_B  26624      // A + B
#define NSTAGE   4
#define GSMEM    106496     // 4 stages

__device__ __forceinline__ uint32_t swa(uint32_t base, int row, int colb) {
    return base + row * 128 + (colb ^ ((row & 7) << 4));
}

// load one stage: A(hi) + B(hi|lo); gmem row stride 512 elems (1024B)
__device__ __forceinline__ void load_stage(uint32_t sb, int s,
    const __half* Ah, const __half* Bh, const __half* Bl,
    int tid, int k0)
{
    const uint32_t st = sb + s * STAGE_B;
    // A: 512 cp.async ops
    #pragma unroll
    for (int it = 0; it < 2; it++) {
        const int op = it * 256 + tid;
        const int r = op >> 2, ch = op & 3;
        cpa16(st + r * 80 + ch * 16,
              (const char*)Ah + (size_t)r * 1024 + (size_t)k0 * 2 + ch * 16);
    }
    // B: 1024 cp.async ops (hi plane p=0, lo plane p=1)
    const __half* bsrc[2] = {Bh, Bl};
    #pragma unroll
    for (int it = 0; it < 4; it++) {
        const int op = it * 256 + tid;
        const int r = op >> 3, sub = op & 7;
        const int p = sub >> 2, ch = sub & 3;
        cpa16(swa(st + A_TILE, r, p * 64 + ch * 16),
              (const char*)bsrc[p] + (size_t)r * 1024 + (size_t)k0 * 2 + ch * 16);
    }
}

__device__ __forceinline__ void compute_k16(uint32_t base, int kk, int lane,
                                            int warp_m, int warp_n, float acc[4][4][4]) {
    uint32_t ah[4][4];
    const int cola = kk + (lane >> 4) * 8;
    #pragma unroll
    for (int mt = 0; mt < 4; mt++) {
        const int row = warp_m * 64 + mt * 16 + (lane & 7) + ((lane >> 3) & 1) * 8;
        ldsm_x4(base + row * 80 + cola * 2, ah[mt]);
    }
    uint32_t bh[2][4], bl[2][4];
    const int colb = kk * 2 + ((lane >> 3) & 1) * 16;
    #pragma unroll
    for (int p = 0; p < 2; p++) {
        const int n = warp_n * 32 + p * 16 + (lane & 7) + (lane >> 4) * 8;
        ldsm_x4(swa(base + A_TILE, n, colb), bh[p]);
        ldsm_x4(swa(base + A_TILE, n, 64 + colb), bl[p]);
    }
    #pragma unroll
    for (int mt = 0; mt < 4; mt++)
        #pragma unroll
        for (int nt = 0; nt < 4; nt++) {
            const uint32_t* bhf = &bh[nt >> 1][(nt & 1) * 2];
            const uint32_t* blf = &bl[nt >> 1][(nt & 1) * 2];
            mma16816(acc[mt][nt], ah[mt], bhf);
            mma16816(acc[mt][nt], ah[mt], blf);
        }
}

// C[128x128] += Ah*(Bh+Bl)^T over K=512; 4-stage pipeline, 1 sync per chunk
__device__ __forceinline__ void gemm_loop(uint32_t sb, int tid,
    const __half* Ah, const __half* Bh, const __half* Bl,
    float acc[4][4][4])
{
    const int lane = tid & 31;
    const int warp_m = (tid >> 5) & 1, warp_n = tid >> 6;

    load_stage(sb, 0, Ah, Bh, Bl, tid, 0);  CP_COMMIT();
    load_stage(sb, 1, Ah, Bh, Bl, tid, 32); CP_COMMIT();
    load_stage(sb, 2, Ah, Bh, Bl, tid, 64); CP_COMMIT();

    #pragma unroll 1
    for (int c = 0; c < 16; c++) {
        if (c + 1 < 16) asm volatile("cp.async.wait_group 2;" ::: "memory");
        else            asm volatile("cp.async.wait_group 0;" ::: "memory");
        __syncthreads();
        if (c + 3 < 16) {
            load_stage(sb, (c + 3) & 3, Ah, Bh, Bl, tid, (c + 3) * 32);
            CP_COMMIT();
        }
        const uint32_t base = sb + (c & 3) * STAGE_B;
        compute_k16(base, 0,  lane, warp_m, warp_n, acc);
        compute_k16(base, 16, lane, warp_m, warp_n, acc);
    }
    __syncthreads();   // protect smem reuse by epilogues
}

// ---------------- pre-pass kernels ----------------
__global__ __launch_bounds__(256)
void prep_x(const float* __restrict__ x1, const float* __restrict__ x2)
{
    int i = blockIdx.x * 256 + threadIdx.x;
    if (i >= BX * D) return;
    g_x1h[i] = __float2half_rn(x1[i]);
    g_x2h[i] = __float2half_rn(x2[i]);
}

// Transpose + split 256*W core: Wt[o][j][i]
__global__ __launch_bounds__(256)
void prep_w(const float* __restrict__ W)
{
    const int o  = blockIdx.z;
    const int i0 = blockIdx.y * 64, j0 = blockIdx.x * 32;
    __shared__ float t[64][33];
    const int tid = threadIdx.x;
    const float* Wo = W + (size_t)o * WSTRIDE;

    #pragma unroll
    for (int p = 0; p < 8; p++) {
        int idx = p * 256 + tid;
        int i = idx >> 5, j = idx & 31;
        t[i][j] = Wo[(size_t)(i0 + i) * 513 + (j0 + j)] * WSCALE;
    }
    __syncthreads();

    const size_t ob = (size_t)o * D * D;
    #pragma unroll
    for (int p = 0; p < 4; p++) {
        const int jl = p * 8 + (tid >> 5);
        const int i2 = (tid & 31) * 2;
        const float v0 = t[i2][jl], v1 = t[i2 + 1][jl];
        const __half h0 = __float2half_rn(v0), h1 = __float2half_rn(v1);
        const size_t off = ob + (size_t)(j0 + jl) * D + i0 + i2;
        *reinterpret_cast<__half2*>(g_Wh + off) = __halves2half2(h0, h1);
        *reinterpret_cast<__half2*>(g_Wl + off) = __halves2half2(
            __float2half_rn(v0 - __half2float(h0)),
            __float2half_rn(v1 - __half2float(h1)));
    }
}

// Combined weights, transposed + split (scaled by 256):
//  Wc[0][o][d] = w0*W[o][d][512] + w1*Wlin[d][o]
//  Wc[1][o][d] = w0*W[o][512][d] + w1*Wlin[D+d][o]
__global__ __launch_bounds__(256)
void comb_w(const float* __restrict__ W, const float* __restrict__ Wlin,
            const float* __restrict__ b_lin, const float* __restrict__ bw)
{
    const int idx = blockIdx.x * 256 + threadIdx.x;   // over 2*O*D
    if (idx >= 2 * O * D) return;
    const float e0 = expf(bw[0]), e1 = expf(bw[1]);
    const float w0 = e0 / (e0 + e1), w1 = e1 / (e0 + e1);

    const int d = idx & 511;
    const int o = (idx >> 9) & 127;
    const int which = idx >> 16;
    const float we = which ? W[(size_t)o * WSTRIDE + (size_t)512 * 513 + d]
                           : W[(size_t)o * WSTRIDE + (size_t)d * 513 + 512];
    const float wl = Wlin[(size_t)(which * D + d) * O + o];
    const float v = (w0 * we + w1 * wl) * WSCALE;
    const __half h = __float2half_rn(v);
    g_WcH[idx] = h;
    g_WcL[idx] = __float2half_rn(v - __half2float(h));

    if (idx < O)          g_bias[idx] = w1 * b_lin[idx];
    else if (idx < 2 * O) {
        const int oo = idx - O;
        g_bias[idx] = w0 * W[(size_t)oo * WSTRIDE + (size_t)512 * 513 + 512];
    }
}

// A-terms via tensor cores: A{1,2}[m, o] = (x @ Wc[which]^T)/256 + bias
__global__ __launch_bounds__(256, 2)
void A_terms_mma()
{
    extern __shared__ char smem[];
    const uint32_t sb = s2u(smem);
    const int tid = threadIdx.x;
    const int m0 = blockIdx.x * 128;
    const int which = blockIdx.y;

    const __half* Ah = (which ? g_x2h : g_x1h) + (size_t)m0 * D;
    const __half* Bh = g_WcH + (size_t)which * O * D;
    const __half* Bl = g_WcL + (size_t)which * O * D;

    float acc[4][4][4] = {};
    gemm_loop(sb, tid, Ah, Bh, Bl, acc);

    float* dst = which ? g_A2 : g_A1;
    const float* bias = g_bias + which * O;
    const int lane = tid & 31;
    const int warp_m = (tid >> 5) & 1, warp_n = tid >> 6;
    #pragma unroll
    for (int mt = 0; mt < 4; mt++)
        #pragma unroll
        for (int nt = 0; nt < 4; nt++) {
            const int oc = warp_n * 32 + nt * 8 + (lane & 3) * 2;
            const float b0 = bias[oc], b1 = bias[oc + 1];
            #pragma unroll
            for (int h = 0; h < 2; h++) {
                const int m = m0 + warp_m * 64 + mt * 16 + (lane >> 2) + h * 8;
                *reinterpret_cast<float2*>(dst + (size_t)m * O + oc) =
                    make_float2(fmaf(acc[mt][nt][h * 2],     INV_WSCALE, b0),
                                fmaf(acc[mt][nt][h * 2 + 1], INV_WSCALE, b1));
            }
        }
}

// ---------------- stage 1: 256*T[m, o, j] = x1[m,:] . (256*Wt[o][j][:]) -----
#define S1_PITCH 272
__global__ __launch_bounds__(256, 2)
void stage1_mma()
{
    extern __shared__ char smem[];
    const uint32_t sb = s2u(smem);
    const int tid = threadIdx.x;
    const int m0 = blockIdx.x * 128;
    const int o  = blockIdx.y >> 2;
    const int j0 = (blockIdx.y & 3) * 128;

    float acc[4][4][4] = {};
    gemm_loop(sb, tid,
              g_x1h + (size_t)m0 * D,
              g_Wh + (size_t)o * D * D + (size_t)j0 * D,
              g_Wl + (size_t)o * D * D + (size_t)j0 * D, acc);

    const int lane = tid & 31;
    const int warp_m = (tid >> 5) & 1, warp_n = tid >> 6;
    #pragma unroll
    for (int mt = 0; mt < 4; mt++)
        #pragma unroll
        for (int nt = 0; nt < 4; nt++)
            #pragma unroll
            for (int h = 0; h < 2; h++) {
                const int ml = warp_m * 64 + mt * 16 + (lane >> 2) + h * 8;
                const int jl = warp_n * 32 + nt * 8 + (lane & 3) * 2;
                const float v0 = acc[mt][nt][h * 2], v1 = acc[mt][nt][h * 2 + 1];
                const __half h0 = __float2half_rn(v0), h1 = __float2half_rn(v1);
                *reinterpret_cast<__half2*>(smem + ml * S1_PITCH + jl * 2) =
                    __halves2half2(h0, h1);
                *reinterpret_cast<__half2*>(smem + 128 * S1_PITCH + ml * S1_PITCH + jl * 2) =
                    __halves2half2(__float2half_rn(v0 - __half2float(h0)),
                                   __float2half_rn(v1 - __half2float(h1)));
            }
    __syncthreads();

    #pragma unroll
    for (int p = 0; p < 8; p++) {
        const int q = p * 256 + tid;
        const int r = q >> 4, c = q & 15;
        const size_t go = ((size_t)(m0 + r) * O + o) * D + j0 + c * 8;
        *reinterpret_cast<uint4*>(g_Th + go) =
            *reinterpret_cast<uint4*>(smem + r * S1_PITCH + c * 16);
        *reinterpret_cast<uint4*>(g_Tl + go) =
            *reinterpret_cast<uint4*>(smem + 128 * S1_PITCH + r * S1_PITCH + c * 16);
    }
}

// ---------------- stage 2: out = (w0/256) * x2 . (256*T[bx]) + A1 + A2 -----
#define S2_PITCH 528
__global__ __launch_bounds__(256, 2)
void stage2_mma(const float* __restrict__ bw, float* __restrict__ out)
{
    extern __shared__ char smem[];
    const uint32_t sb = s2u(smem);
    const int tid = threadIdx.x;
    const int y0 = blockIdx.x * 128;
    const int bx = blockIdx.y;
    const int b  = bx >> 8;
    const size_t arow = (size_t)(b * L + y0) * D;

    float acc[4][4][4] = {};
    gemm_loop(sb, tid,
              g_x2h + arow,
              g_Th + (size_t)bx * O * D, g_Tl + (size_t)bx * O * D, acc);

    const int lane = tid & 31;
    const int warp_m = (tid >> 5) & 1, warp_n = tid >> 6;
    #pragma unroll
    for (int mt = 0; mt < 4; mt++)
        #pragma unroll
        for (int nt = 0; nt < 4; nt++)
            #pragma unroll
            for (int h = 0; h < 2; h++) {
                const int yl = warp_m * 64 + mt * 16 + (lane >> 2) + h * 8;
                const int ol = warp_n * 32 + nt * 8 + (lane & 3) * 2;
                *reinterpret_cast<float2*>(smem + yl * S2_PITCH + ol * 4) =
                    make_float2(acc[mt][nt][h * 2], acc[mt][nt][h * 2 + 1]);
            }
    __syncthreads();

    const float e0 = expf(bw[0]), e1 = expf(bw[1]);
    const float w0s = (e0 / (e0 + e1)) * INV_WSCALE;

    #pragma unroll
    for (int p = 0; p < 16; p++) {
        const int q = p * 256 + tid;
        const int r = q >> 5, c = q & 31;
        const float4 v = *reinterpret_cast<float4*>(smem + r * S2_PITCH + c * 16);
        const float4 a1 = *reinterpret_cast<const float4*>(g_A1 + (size_t)bx * O + c * 4);
        const float4 a2 = *reinterpret_cast<const float4*>(g_A2 + (size_t)(b * L + y0 + r) * O + c * 4);
        float4 rr;
        rr.x = fmaf(w0s, v.x, a1.x + a2.x);
        rr.y = fmaf(w0s, v.y, a1.y + a2.y);
        rr.z = fmaf(w0s, v.z, a1.z + a2.z);
        rr.w = fmaf(w0s, v.w, a1.w + a2.w);
        *reinterpret_cast<float4*>(out + ((size_t)bx * L + y0 + r) * O + c * 4) = rr;
    }
}

// ---------------------------------------------------------------------------
extern "C" void kernel_launch(void* const* d_in, const int* in_sizes, int n_in,
                              void* d_out, int out_size)
{
    const float* x1    = (const float*)d_in[0];
    const float* x2    = (const float*)d_in[1];
    const float* bw    = (const float*)d_in[2];
    const float* W_bil = (const float*)d_in[3];
    const float* W_lin = (const float*)d_in[4];
    const float* b_lin = (const float*)d_in[5];
    float* out = (float*)d_out;

    cudaFuncSetAttribute(A_terms_mma, cudaFuncAttributeMaxDynamicSharedMemorySize, GSMEM);
    cudaFuncSetAttribute(stage1_mma,  cudaFuncAttributeMaxDynamicSharedMemorySize, GSMEM);
    cudaFuncSetAttribute(stage2_mma,  cudaFuncAttributeMaxDynamicSharedMemorySize, GSMEM);

    prep_x<<<(BX * D + 255) / 256, 256>>>(x1, x2);
    prep_w<<<dim3(16, 8, O), 256>>>(W_bil);
    comb_w<<<(2 * O * D + 255) / 256, 256>>>(W_bil, W_lin, b_lin, bw);
    A_terms_mma<<<dim3(8, 2), 256, GSMEM>>>();

    stage1_mma<<<dim3(8, 512), 256, GSMEM>>>();
    stage2_mma<<<dim3(2, BX), 256, GSMEM>>>(bw, out);
}

// round 9
// speedup vs baseline: 9.4945x; 1.5105x over previous
#include <cuda_runtime.h>
#include <cuda_fp16.h>
#include <cstdint>
#include <cstddef>
#include <math.h>

#define B 4
#define L 256
#define D 512
#define O 128
#define BX 1024
#define WSTRIDE 263169       // 513*513
#define WSCALE 256.0f
#define INV_WSCALE (1.0f/256.0f)

// ---------------- device scratch (static, no runtime alloc) ----------------
__device__ __half g_x1h[BX * D];
__device__ __half g_x2h[BX * D];
__device__ __half g_Wh[(size_t)O * D * D];   // 256*Wt[o][j][i]
__device__ __half g_Th[(size_t)BX * O * D];  // 256*T[bx][o][j]
__device__ __half g_WcH[2 * O * D];          // 256*Wc[which][o][d], hi
__device__ __half g_WcL[2 * O * D];          // lo residual
__device__ float g_bias[2 * O];    // [0][o]: w1*b_lin, [1][o]: w0*corner
__device__ float g_A1[BX * O];
__device__ float g_A2[BX * O];

// ---------------- low-level helpers ----------------
__device__ __forceinline__ uint32_t s2u(const void* p) {
    uint32_t a;
    asm("{ .reg .u64 t; cvta.to.shared.u64 t, %1; cvt.u32.u64 %0, t; }" : "=r"(a) : "l"(p));
    return a;
}
__device__ __forceinline__ void cpa16(uint32_t d, const void* s) {
    asm volatile("cp.async.cg.shared.global [%0], [%1], 16;" :: "r"(d), "l"(s) : "memory");
}
#define CP_COMMIT() asm volatile("cp.async.commit_group;" ::: "memory")

__device__ __forceinline__ void ldsm_x4(uint32_t a, uint32_t r[4]) {
    asm volatile("ldmatrix.sync.aligned.m8n8.x4.shared.b16 {%0,%1,%2,%3}, [%4];"
                 : "=r"(r[0]), "=r"(r[1]), "=r"(r[2]), "=r"(r[3]) : "r"(a));
}
__device__ __forceinline__ void mma16816(float c[4], const uint32_t a[4], const uint32_t b[2]) {
    asm volatile(
        "mma.sync.aligned.m16n8k16.row.col.f32.f16.f16.f32 "
        "{%0,%1,%2,%3}, {%4,%5,%6,%7}, {%8,%9}, {%0,%1,%2,%3};"
        : "+f"(c[0]), "+f"(c[1]), "+f"(c[2]), "+f"(c[3])
        : "r"(a[0]), "r"(a[1]), "r"(a[2]), "r"(a[3]), "r"(b[0]), "r"(b[1]));
}

// ---- tiles per BK=32 chunk: each plane 128 rows x 32 fp16 (64B) + 16B pad -> 80B stride
// (row-phase bank walk {0,20,8,28,16,4,24,12} -> conflict-free ldsm + cp.async)
#define PLANE_B  10240      // 128*80
// NP = number of B planes (1 = hi only, 2 = hi+lo)
#define NSTAGE   4
#define GSMEM1   (4 * (PLANE_B * 2))   // 81920  (stage kernels, occ 2)
#define GSMEM2   (4 * (PLANE_B * 3))   // 122880 (A-terms, occ 1)

// load one stage: A plane + NP B planes; gmem row stride 512 elems (1024B)
template <int NP>
__device__ __forceinline__ void load_stage(uint32_t sb, int s,
    const __half* Ah, const __half* Bh, const __half* Bl,
    int tid, int k0)
{
    const uint32_t st = sb + s * (PLANE_B * (1 + NP));
    #pragma unroll
    for (int it = 0; it < 2; it++) {
        const int op = it * 256 + tid;
        const int r = op >> 2, ch = op & 3;
        const size_t goff = (size_t)r * 1024 + (size_t)k0 * 2 + ch * 16;
        cpa16(st + r * 80 + ch * 16, (const char*)Ah + goff);
        cpa16(st + PLANE_B + r * 80 + ch * 16, (const char*)Bh + goff);
        if (NP == 2)
            cpa16(st + 2 * PLANE_B + r * 80 + ch * 16, (const char*)Bl + goff);
    }
}

template <int NP>
__device__ __forceinline__ void compute_k16(uint32_t base, int kk, int lane,
                                            int warp_m, int warp_n, float acc[4][4][4]) {
    uint32_t ah[4][4];
    const int cola = kk + (lane >> 4) * 8;
    #pragma unroll
    for (int mt = 0; mt < 4; mt++) {
        const int row = warp_m * 64 + mt * 16 + (lane & 7) + ((lane >> 3) & 1) * 8;
        ldsm_x4(base + row * 80 + cola * 2, ah[mt]);
    }
    uint32_t bh[2][4], bl[2][4];
    const int colb = kk + ((lane >> 3) & 1) * 8;
    #pragma unroll
    for (int p = 0; p < 2; p++) {
        const int n = warp_n * 32 + p * 16 + (lane & 7) + (lane >> 4) * 8;
        ldsm_x4(base + PLANE_B + n * 80 + colb * 2, bh[p]);
        if (NP == 2)
            ldsm_x4(base + 2 * PLANE_B + n * 80 + colb * 2, bl[p]);
    }
    #pragma unroll
    for (int mt = 0; mt < 4; mt++)
        #pragma unroll
        for (int nt = 0; nt < 4; nt++) {
            mma16816(acc[mt][nt], ah[mt], &bh[nt >> 1][(nt & 1) * 2]);
            if (NP == 2)
                mma16816(acc[mt][nt], ah[mt], &bl[nt >> 1][(nt & 1) * 2]);
        }
}

// C[128x128] += Ah*B^T over K=512; 4-stage pipeline, 1 sync per chunk
template <int NP>
__device__ __forceinline__ void gemm_loop(uint32_t sb, int tid,
    const __half* Ah, const __half* Bh, const __half* Bl,
    float acc[4][4][4])
{
    const int lane = tid & 31;
    const int warp_m = (tid >> 5) & 1, warp_n = tid >> 6;
    const int stage_b = PLANE_B * (1 + NP);

    load_stage<NP>(sb, 0, Ah, Bh, Bl, tid, 0);  CP_COMMIT();
    load_stage<NP>(sb, 1, Ah, Bh, Bl, tid, 32); CP_COMMIT();
    load_stage<NP>(sb, 2, Ah, Bh, Bl, tid, 64); CP_COMMIT();

    #pragma unroll 1
    for (int c = 0; c < 16; c++) {
        if (c + 1 < 16) asm volatile("cp.async.wait_group 2;" ::: "memory");
        else            asm volatile("cp.async.wait_group 0;" ::: "memory");
        __syncthreads();
        if (c + 3 < 16) {
            load_stage<NP>(sb, (c + 3) & 3, Ah, Bh, Bl, tid, (c + 3) * 32);
            CP_COMMIT();
        }
        const uint32_t base = sb + (c & 3) * stage_b;
        compute_k16<NP>(base, 0,  lane, warp_m, warp_n, acc);
        compute_k16<NP>(base, 16, lane, warp_m, warp_n, acc);
    }
    __syncthreads();   // protect smem reuse by epilogues
}

// ---------------- pre-pass kernels ----------------
__global__ __launch_bounds__(256)
void prep_x(const float* __restrict__ x1, const float* __restrict__ x2)
{
    int i = blockIdx.x * 256 + threadIdx.x;
    if (i >= BX * D) return;
    g_x1h[i] = __float2half_rn(x1[i]);
    g_x2h[i] = __float2half_rn(x2[i]);
}

// Transpose 256*W core: Wt[o][j][i] (single fp16 plane)
__global__ __launch_bounds__(256)
void prep_w(const float* __restrict__ W)
{
    const int o  = blockIdx.z;
    const int i0 = blockIdx.y * 64, j0 = blockIdx.x * 32;
    __shared__ float t[64][33];
    const int tid = threadIdx.x;
    const float* Wo = W + (size_t)o * WSTRIDE;

    #pragma unroll
    for (int p = 0; p < 8; p++) {
        int idx = p * 256 + tid;
        int i = idx >> 5, j = idx & 31;
        t[i][j] = Wo[(size_t)(i0 + i) * 513 + (j0 + j)] * WSCALE;
    }
    __syncthreads();

    const size_t ob = (size_t)o * D * D;
    #pragma unroll
    for (int p = 0; p < 4; p++) {
        const int jl = p * 8 + (tid >> 5);
        const int i2 = (tid & 31) * 2;
        const size_t off = ob + (size_t)(j0 + jl) * D + i0 + i2;
        *reinterpret_cast<__half2*>(g_Wh + off) =
            __halves2half2(__float2half_rn(t[i2][jl]), __float2half_rn(t[i2 + 1][jl]));
    }
}

// Combined weights, transposed + split (scaled by 256):
//  Wc[0][o][d] = w0*W[o][d][512] + w1*Wlin[d][o]
//  Wc[1][o][d] = w0*W[o][512][d] + w1*Wlin[D+d][o]
__global__ __launch_bounds__(256)
void comb_w(const float* __restrict__ W, const float* __restrict__ Wlin,
            const float* __restrict__ b_lin, const float* __restrict__ bw)
{
    const int idx = blockIdx.x * 256 + threadIdx.x;   // over 2*O*D
    if (idx >= 2 * O * D) return;
    const float e0 = expf(bw[0]), e1 = expf(bw[1]);
    const float w0 = e0 / (e0 + e1), w1 = e1 / (e0 + e1);

    const int d = idx & 511;
    const int o = (idx >> 9) & 127;
    const int which = idx >> 16;
    const float we = which ? W[(size_t)o * WSTRIDE + (size_t)512 * 513 + d]
                           : W[(size_t)o * WSTRIDE + (size_t)d * 513 + 512];
    const float wl = Wlin[(size_t)(which * D + d) * O + o];
    const float v = (w0 * we + w1 * wl) * WSCALE;
    const __half h = __float2half_rn(v);
    g_WcH[idx] = h;
    g_WcL[idx] = __float2half_rn(v - __half2float(h));

    if (idx < O)          g_bias[idx] = w1 * b_lin[idx];
    else if (idx < 2 * O) {
        const int oo = idx - O;
        g_bias[idx] = w0 * W[(size_t)oo * WSTRIDE + (size_t)512 * 513 + 512];
    }
}

// A-terms via tensor cores (2-plane Wc): A{1,2}[m,o] = (x @ Wc^T)/256 + bias
__global__ __launch_bounds__(256, 1)
void A_terms_mma()
{
    extern __shared__ char smem[];
    const uint32_t sb = s2u(smem);
    const int tid = threadIdx.x;
    const int m0 = blockIdx.x * 128;
    const int which = blockIdx.y;

    const __half* Ah = (which ? g_x2h : g_x1h) + (size_t)m0 * D;
    const __half* Bh = g_WcH + (size_t)which * O * D;
    const __half* Bl = g_WcL + (size_t)which * O * D;

    float acc[4][4][4] = {};
    gemm_loop<2>(sb, tid, Ah, Bh, Bl, acc);

    float* dst = which ? g_A2 : g_A1;
    const float* bias = g_bias + which * O;
    const int lane = tid & 31;
    const int warp_m = (tid >> 5) & 1, warp_n = tid >> 6;
    #pragma unroll
    for (int mt = 0; mt < 4; mt++)
        #pragma unroll
        for (int nt = 0; nt < 4; nt++) {
            const int oc = warp_n * 32 + nt * 8 + (lane & 3) * 2;
            const float b0 = bias[oc], b1 = bias[oc + 1];
            #pragma unroll
            for (int h = 0; h < 2; h++) {
                const int m = m0 + warp_m * 64 + mt * 16 + (lane >> 2) + h * 8;
                *reinterpret_cast<float2*>(dst + (size_t)m * O + oc) =
                    make_float2(fmaf(acc[mt][nt][h * 2],     INV_WSCALE, b0),
                                fmaf(acc[mt][nt][h * 2 + 1], INV_WSCALE, b1));
            }
        }
}

// ---------------- stage 1: 256*T[m, o, j] = x1[m,:] . (256*Wt[o][j][:]) -----
#define S1_PITCH 272
__global__ __launch_bounds__(256, 2)
void stage1_mma()
{
    extern __shared__ char smem[];
    const uint32_t sb = s2u(smem);
    const int tid = threadIdx.x;
    const int m0 = blockIdx.x * 128;
    const int o  = blockIdx.y >> 2;
    const int j0 = (blockIdx.y & 3) * 128;

    float acc[4][4][4] = {};
    gemm_loop<1>(sb, tid,
                 g_x1h + (size_t)m0 * D,
                 g_Wh + (size_t)o * D * D + (size_t)j0 * D, nullptr, acc);

    const int lane = tid & 31;
    const int warp_m = (tid >> 5) & 1, warp_n = tid >> 6;
    #pragma unroll
    for (int mt = 0; mt < 4; mt++)
        #pragma unroll
        for (int nt = 0; nt < 4; nt++)
            #pragma unroll
            for (int h = 0; h < 2; h++) {
                const int ml = warp_m * 64 + mt * 16 + (lane >> 2) + h * 8;
                const int jl = warp_n * 32 + nt * 8 + (lane & 3) * 2;
                *reinterpret_cast<__half2*>(smem + ml * S1_PITCH + jl * 2) =
                    __halves2half2(__float2half_rn(acc[mt][nt][h * 2]),
                                   __float2half_rn(acc[mt][nt][h * 2 + 1]));
            }
    __syncthreads();

    #pragma unroll
    for (int p = 0; p < 8; p++) {
        const int q = p * 256 + tid;
        const int r = q >> 4, c = q & 15;
        const size_t go = ((size_t)(m0 + r) * O + o) * D + j0 + c * 8;
        *reinterpret_cast<uint4*>(g_Th + go) =
            *reinterpret_cast<uint4*>(smem + r * S1_PITCH + c * 16);
    }
}

// ---------------- stage 2: out = (w0/256) * x2 . (256*T[bx]) + A1 + A2 -----
#define S2_PITCH 528
__global__ __launch_bounds__(256, 2)
void stage2_mma(const float* __restrict__ bw, float* __restrict__ out)
{
    extern __shared__ char smem[];
    const uint32_t sb = s2u(smem);
    const int tid = threadIdx.x;
    const int y0 = blockIdx.x * 128;
    const int bx = blockIdx.y;
    const int b  = bx >> 8;
    const size_t arow = (size_t)(b * L + y0) * D;

    float acc[4][4][4] = {};
    gemm_loop<1>(sb, tid,
                 g_x2h + arow,
                 g_Th + (size_t)bx * O * D, nullptr, acc);

    const int lane = tid & 31;
    const int warp_m = (tid >> 5) & 1, warp_n = tid >> 6;
    #pragma unroll
    for (int mt = 0; mt < 4; mt++)
        #pragma unroll
        for (int nt = 0; nt < 4; nt++)
            #pragma unroll
            for (int h = 0; h < 2; h++) {
                const int yl = warp_m * 64 + mt * 16 + (lane >> 2) + h * 8;
                const int ol = warp_n * 32 + nt * 8 + (lane & 3) * 2;
                *reinterpret_cast<float2*>(smem + yl * S2_PITCH + ol * 4) =
                    make_float2(acc[mt][nt][h * 2], acc[mt][nt][h * 2 + 1]);
            }
    __syncthreads();

    const float e0 = expf(bw[0]), e1 = expf(bw[1]);
    const float w0s = (e0 / (e0 + e1)) * INV_WSCALE;

    #pragma unroll
    for (int p = 0; p < 16; p++) {
        const int q = p * 256 + tid;
        const int r = q >> 5, c = q & 31;
        const float4 v = *reinterpret_cast<float4*>(smem + r * S2_PITCH + c * 16);
        const float4 a1 = *reinterpret_cast<const float4*>(g_A1 + (size_t)bx * O + c * 4);
        const float4 a2 = *reinterpret_cast<const float4*>(g_A2 + (size_t)(b * L + y0 + r) * O + c * 4);
        float4 rr;
        rr.x = fmaf(w0s, v.x, a1.x + a2.x);
        rr.y = fmaf(w0s, v.y, a1.y + a2.y);
        rr.z = fmaf(w0s, v.z, a1.z + a2.z);
        rr.w = fmaf(w0s, v.w, a1.w + a2.w);
        *reinterpret_cast<float4*>(out + ((size_t)bx * L + y0 + r) * O + c * 4) = rr;
    }
}

// ---------------------------------------------------------------------------
extern "C" void kernel_launch(void* const* d_in, const int* in_sizes, int n_in,
                              void* d_out, int out_size)
{
    const float* x1    = (const float*)d_in[0];
    const float* x2    = (const float*)d_in[1];
    const float* bw    = (const float*)d_in[2];
    const float* W_bil = (const float*)d_in[3];
    const float* W_lin = (const float*)d_in[4];
    const float* b_lin = (const float*)d_in[5];
    float* out = (float*)d_out;

    cudaFuncSetAttribute(A_terms_mma, cudaFuncAttributeMaxDynamicSharedMemorySize, GSMEM2);
    cudaFuncSetAttribute(stage1_mma,  cudaFuncAttributeMaxDynamicSharedMemorySize, GSMEM1);
    cudaFuncSetAttribute(stage2_mma,  cudaFuncAttributeMaxDynamicSharedMemorySize, GSMEM1);

    prep_x<<<(BX * D + 255) / 256, 256>>>(x1, x2);
    prep_w<<<dim3(16, 8, O), 256>>>(W_bil);
    comb_w<<<(2 * O * D + 255) / 256, 256>>>(W_bil, W_lin, b_lin, bw);
    A_terms_mma<<<dim3(8, 2), 256, GSMEM2>>>();

    stage1_mma<<<dim3(8, 512), 256, GSMEM1>>>();
    stage2_mma<<<dim3(2, BX), 256, GSMEM1>>>(bw, out);
}

// round 10
// speedup vs baseline: 10.7380x; 1.1310x over previous
#include <cuda_runtime.h>
#include <cuda_fp16.h>
#include <cstdint>
#include <cstddef>
#include <math.h>

#define B 4
#define L 256
#define D 512
#define O 128
#define BX 1024
#define WSTRIDE 263169       // 513*513
#define WSCALE 256.0f
#define INV_WSCALE (1.0f/256.0f)

// ---------------- device scratch (static, no runtime alloc) ----------------
__device__ __half g_x1h[BX * D];
__device__ __half g_x2h[BX * D];
__device__ __half g_Wh[(size_t)O * D * D];   // 256*Wt[o][j][i]
__device__ __half g_Th[(size_t)BX * O * D];  // 256*T[bx][o][j]
__device__ __half g_WcH[2 * O * D];          // 256*Wc[which][o][d]
__device__ float g_bias[2 * O];    // [0][o]: w1*b_lin, [1][o]: w0*corner
__device__ float g_A1[BX * O];
__device__ float g_A2[BX * O];

// ---------------- low-level helpers ----------------
__device__ __forceinline__ uint32_t s2u(const void* p) {
    uint32_t a;
    asm("{ .reg .u64 t; cvta.to.shared.u64 t, %1; cvt.u32.u64 %0, t; }" : "=r"(a) : "l"(p));
    return a;
}
__device__ __forceinline__ void cpa16(uint32_t d, const void* s) {
    asm volatile("cp.async.cg.shared.global [%0], [%1], 16;" :: "r"(d), "l"(s) : "memory");
}
#define CP_COMMIT() asm volatile("cp.async.commit_group;" ::: "memory")

__device__ __forceinline__ void ldsm_x4(uint32_t a, uint32_t r[4]) {
    asm volatile("ldmatrix.sync.aligned.m8n8.x4.shared.b16 {%0,%1,%2,%3}, [%4];"
                 : "=r"(r[0]), "=r"(r[1]), "=r"(r[2]), "=r"(r[3]) : "r"(a));
}
__device__ __forceinline__ void mma16816(float c[4], const uint32_t a[4], const uint32_t b[2]) {
    asm volatile(
        "mma.sync.aligned.m16n8k16.row.col.f32.f16.f16.f32 "
        "{%0,%1,%2,%3}, {%4,%5,%6,%7}, {%8,%9}, {%0,%1,%2,%3};"
        : "+f"(c[0]), "+f"(c[1]), "+f"(c[2]), "+f"(c[3])
        : "r"(a[0]), "r"(a[1]), "r"(a[2]), "r"(a[3]), "r"(b[0]), "r"(b[1]));
}

// ---- tiles per BK=64 chunk: plane = 128 rows x 64 fp16 (128B) + 16B pad -> 144B stride
// (stride = 9 x 16B units, gcd(9,8)=1 -> conflict-free ldsm + cp.async)
#define PLANE_B  18432      // 128*144
#define STAGE_B  36864      // A plane + B plane
#define NSTAGE   3
#define GSMEM    110592     // 3 stages -> occ 2 (221KB/SM)

// load one stage: A plane + B plane; gmem row stride 512 elems (1024B)
__device__ __forceinline__ void load_stage(uint32_t sb, int s,
    const __half* Ah, const __half* Bh, int tid, int k0)
{
    const uint32_t st = sb + s * STAGE_B;
    #pragma unroll
    for (int it = 0; it < 4; it++) {
        const int op = it * 256 + tid;          // 0..1023
        const int r = op >> 3, ch = op & 7;
        const size_t goff = (size_t)r * 1024 + (size_t)k0 * 2 + ch * 16;
        cpa16(st + r * 144 + ch * 16, (const char*)Ah + goff);
        cpa16(st + PLANE_B + r * 144 + ch * 16, (const char*)Bh + goff);
    }
}

__device__ __forceinline__ void compute_k16(uint32_t base, int kk, int lane,
                                            int warp_m, int warp_n, float acc[4][4][4]) {
    uint32_t ah[4][4];
    const int cola = kk + (lane >> 4) * 8;
    #pragma unroll
    for (int mt = 0; mt < 4; mt++) {
        const int row = warp_m * 64 + mt * 16 + (lane & 7) + ((lane >> 3) & 1) * 8;
        ldsm_x4(base + row * 144 + cola * 2, ah[mt]);
    }
    uint32_t bh[2][4];
    const int colb = kk + ((lane >> 3) & 1) * 8;
    #pragma unroll
    for (int p = 0; p < 2; p++) {
        const int n = warp_n * 32 + p * 16 + (lane & 7) + (lane >> 4) * 8;
        ldsm_x4(base + PLANE_B + n * 144 + colb * 2, bh[p]);
    }
    #pragma unroll
    for (int mt = 0; mt < 4; mt++)
        #pragma unroll
        for (int nt = 0; nt < 4; nt++)
            mma16816(acc[mt][nt], ah[mt], &bh[nt >> 1][(nt & 1) * 2]);
}

// C[128x128] += A*B^T over K=512; BK=64, 3-stage pipeline, 1 sync per chunk (8 total)
__device__ __forceinline__ void gemm_loop(uint32_t sb, int tid,
    const __half* Ah, const __half* Bh, float acc[4][4][4])
{
    const int lane = tid & 31;
    const int warp_m = (tid >> 5) & 1, warp_n = tid >> 6;

    load_stage(sb, 0, Ah, Bh, tid, 0);  CP_COMMIT();
    load_stage(sb, 1, Ah, Bh, tid, 64); CP_COMMIT();

    int s_c = 0, s_n = 2;   // compute-stage, next-load-stage indices (mod 3)
    #pragma unroll 1
    for (int c = 0; c < 8; c++) {
        if (c + 1 < 8) asm volatile("cp.async.wait_group 1;" ::: "memory");
        else           asm volatile("cp.async.wait_group 0;" ::: "memory");
        __syncthreads();
        if (c + 2 < 8) {
            load_stage(sb, s_n, Ah, Bh, tid, (c + 2) * 64);
            CP_COMMIT();
            if (++s_n == NSTAGE) s_n = 0;
        }
        const uint32_t base = sb + s_c * STAGE_B;
        compute_k16(base, 0,  lane, warp_m, warp_n, acc);
        compute_k16(base, 16, lane, warp_m, warp_n, acc);
        compute_k16(base, 32, lane, warp_m, warp_n, acc);
        compute_k16(base, 48, lane, warp_m, warp_n, acc);
        if (++s_c == NSTAGE) s_c = 0;
    }
    __syncthreads();   // protect smem reuse by epilogues
}

// ---------------- pre-pass kernels ----------------
__global__ __launch_bounds__(256)
void prep_x(const float* __restrict__ x1, const float* __restrict__ x2)
{
    int i = blockIdx.x * 256 + threadIdx.x;
    if (i >= BX * D) return;
    g_x1h[i] = __float2half_rn(x1[i]);
    g_x2h[i] = __float2half_rn(x2[i]);
}

// Transpose 256*W core: Wt[o][j][i] (single fp16 plane)
__global__ __launch_bounds__(256)
void prep_w(const float* __restrict__ W)
{
    const int o  = blockIdx.z;
    const int i0 = blockIdx.y * 64, j0 = blockIdx.x * 32;
    __shared__ float t[64][33];
    const int tid = threadIdx.x;
    const float* Wo = W + (size_t)o * WSTRIDE;

    #pragma unroll
    for (int p = 0; p < 8; p++) {
        int idx = p * 256 + tid;
        int i = idx >> 5, j = idx & 31;
        t[i][j] = Wo[(size_t)(i0 + i) * 513 + (j0 + j)] * WSCALE;
    }
    __syncthreads();

    const size_t ob = (size_t)o * D * D;
    #pragma unroll
    for (int p = 0; p < 4; p++) {
        const int jl = p * 8 + (tid >> 5);
        const int i2 = (tid & 31) * 2;
        const size_t off = ob + (size_t)(j0 + jl) * D + i0 + i2;
        *reinterpret_cast<__half2*>(g_Wh + off) =
            __halves2half2(__float2half_rn(t[i2][jl]), __float2half_rn(t[i2 + 1][jl]));
    }
}

// Combined weights (scaled by 256), single plane:
//  Wc[0][o][d] = w0*W[o][d][512] + w1*Wlin[d][o]
//  Wc[1][o][d] = w0*W[o][512][d] + w1*Wlin[D+d][o]
__global__ __launch_bounds__(256)
void comb_w(const float* __restrict__ W, const float* __restrict__ Wlin,
            const float* __restrict__ b_lin, const float* __restrict__ bw)
{
    const int idx = blockIdx.x * 256 + threadIdx.x;   // over 2*O*D
    if (idx >= 2 * O * D) return;
    const float e0 = expf(bw[0]), e1 = expf(bw[1]);
    const float w0 = e0 / (e0 + e1), w1 = e1 / (e0 + e1);

    const int d = idx & 511;
    const int o = (idx >> 9) & 127;
    const int which = idx >> 16;
    const float we = which ? W[(size_t)o * WSTRIDE + (size_t)512 * 513 + d]
                           : W[(size_t)o * WSTRIDE + (size_t)d * 513 + 512];
    const float wl = Wlin[(size_t)(which * D + d) * O + o];
    g_WcH[idx] = __float2half_rn((w0 * we + w1 * wl) * WSCALE);

    if (idx < O)          g_bias[idx] = w1 * b_lin[idx];
    else if (idx < 2 * O) {
        const int oo = idx - O;
        g_bias[idx] = w0 * W[(size_t)oo * WSTRIDE + (size_t)512 * 513 + 512];
    }
}

// A-terms via tensor cores: A{1,2}[m,o] = (x @ Wc^T)/256 + bias
__global__ __launch_bounds__(256, 2)
void A_terms_mma()
{
    extern __shared__ char smem[];
    const uint32_t sb = s2u(smem);
    const int tid = threadIdx.x;
    const int m0 = blockIdx.x * 128;
    const int which = blockIdx.y;

    const __half* Ah = (which ? g_x2h : g_x1h) + (size_t)m0 * D;
    const __half* Bh = g_WcH + (size_t)which * O * D;

    float acc[4][4][4] = {};
    gemm_loop(sb, tid, Ah, Bh, acc);

    float* dst = which ? g_A2 : g_A1;
    const float* bias = g_bias + which * O;
    const int lane = tid & 31;
    const int warp_m = (tid >> 5) & 1, warp_n = tid >> 6;
    #pragma unroll
    for (int mt = 0; mt < 4; mt++)
        #pragma unroll
        for (int nt = 0; nt < 4; nt++) {
            const int oc = warp_n * 32 + nt * 8 + (lane & 3) * 2;
            const float b0 = bias[oc], b1 = bias[oc + 1];
            #pragma unroll
            for (int h = 0; h < 2; h++) {
                const int m = m0 + warp_m * 64 + mt * 16 + (lane >> 2) + h * 8;
                *reinterpret_cast<float2*>(dst + (size_t)m * O + oc) =
                    make_float2(fmaf(acc[mt][nt][h * 2],     INV_WSCALE, b0),
                                fmaf(acc[mt][nt][h * 2 + 1], INV_WSCALE, b1));
            }
        }
}

// ---------------- stage 1: 256*T[m, o, j] = x1[m,:] . (256*Wt[o][j][:]) -----
#define S1_PITCH 272
__global__ __launch_bounds__(256, 2)
void stage1_mma()
{
    extern __shared__ char smem[];
    const uint32_t sb = s2u(smem);
    const int tid = threadIdx.x;
    const int m0 = blockIdx.x * 128;
    const int o  = blockIdx.y >> 2;
    const int j0 = (blockIdx.y & 3) * 128;

    float acc[4][4][4] = {};
    gemm_loop(sb, tid,
              g_x1h + (size_t)m0 * D,
              g_Wh + (size_t)o * D * D + (size_t)j0 * D, acc);

    const int lane = tid & 31;
    const int warp_m = (tid >> 5) & 1, warp_n = tid >> 6;
    #pragma unroll
    for (int mt = 0; mt < 4; mt++)
        #pragma unroll
        for (int nt = 0; nt < 4; nt++)
            #pragma unroll
            for (int h = 0; h < 2; h++) {
                const int ml = warp_m * 64 + mt * 16 + (lane >> 2) + h * 8;
                const int jl = warp_n * 32 + nt * 8 + (lane & 3) * 2;
                *reinterpret_cast<__half2*>(smem + ml * S1_PITCH + jl * 2) =
                    __halves2half2(__float2half_rn(acc[mt][nt][h * 2]),
                                   __float2half_rn(acc[mt][nt][h * 2 + 1]));
            }
    __syncthreads();

    #pragma unroll
    for (int p = 0; p < 8; p++) {
        const int q = p * 256 + tid;
        const int r = q >> 4, c = q & 15;
        const size_t go = ((size_t)(m0 + r) * O + o) * D + j0 + c * 8;
        *reinterpret_cast<uint4*>(g_Th + go) =
            *reinterpret_cast<uint4*>(smem + r * S1_PITCH + c * 16);
    }
}

// ---------------- stage 2: out = (w0/256) * x2 . (256*T[bx]) + A1 + A2 -----
#define S2_PITCH 528
__global__ __launch_bounds__(256, 2)
void stage2_mma(const float* __restrict__ bw, float* __restrict__ out)
{
    extern __shared__ char smem[];
    const uint32_t sb = s2u(smem);
    const int tid = threadIdx.x;
    const int y0 = blockIdx.x * 128;
    const int bx = blockIdx.y;
    const int b  = bx >> 8;
    const size_t arow = (size_t)(b * L + y0) * D;

    float acc[4][4][4] = {};
    gemm_loop(sb, tid,
              g_x2h + arow,
              g_Th + (size_t)bx * O * D, acc);

    const int lane = tid & 31;
    const int warp_m = (tid >> 5) & 1, warp_n = tid >> 6;
    #pragma unroll
    for (int mt = 0; mt < 4; mt++)
        #pragma unroll
        for (int nt = 0; nt < 4; nt++)
            #pragma unroll
            for (int h = 0; h < 2; h++) {
                const int yl = warp_m * 64 + mt * 16 + (lane >> 2) + h * 8;
                const int ol = warp_n * 32 + nt * 8 + (lane & 3) * 2;
                *reinterpret_cast<float2*>(smem + yl * S2_PITCH + ol * 4) =
                    make_float2(acc[mt][nt][h * 2], acc[mt][nt][h * 2 + 1]);
            }
    __syncthreads();

    const float e0 = expf(bw[0]), e1 = expf(bw[1]);
    const float w0s = (e0 / (e0 + e1)) * INV_WSCALE;

    #pragma unroll
    for (int p = 0; p < 16; p++) {
        const int q = p * 256 + tid;
        const int r = q >> 5, c = q & 31;
        const float4 v = *reinterpret_cast<float4*>(smem + r * S2_PITCH + c * 16);
        const float4 a1 = *reinterpret_cast<const float4*>(g_A1 + (size_t)bx * O + c * 4);
        const float4 a2 = *reinterpret_cast<const float4*>(g_A2 + (size_t)(b * L + y0 + r) * O + c * 4);
        float4 rr;
        rr.x = fmaf(w0s, v.x, a1.x + a2.x);
        rr.y = fmaf(w0s, v.y, a1.y + a2.y);
        rr.z = fmaf(w0s, v.z, a1.z + a2.z);
        rr.w = fmaf(w0s, v.w, a1.w + a2.w);
        *reinterpret_cast<float4*>(out + ((size_t)bx * L + y0 + r) * O + c * 4) = rr;
    }
}

// ---------------------------------------------------------------------------
extern "C" void kernel_launch(void* const* d_in, const int* in_sizes, int n_in,
                              void* d_out, int out_size)
{
    const float* x1    = (const float*)d_in[0];
    const float* x2    = (const float*)d_in[1];
    const float* bw    = (const float*)d_in[2];
    const float* W_bil = (const float*)d_in[3];
    const float* W_lin = (const float*)d_in[4];
    const float* b_lin = (const float*)d_in[5];
    float* out = (float*)d_out;

    cudaFuncSetAttribute(A_terms_mma, cudaFuncAttributeMaxDynamicSharedMemorySize, GSMEM);
    cudaFuncSetAttribute(stage1_mma,  cudaFuncAttributeMaxDynamicSharedMemorySize, GSMEM);
    cudaFuncSetAttribute(stage2_mma,  cudaFuncAttributeMaxDynamicSharedMemorySize, GSMEM);

    prep_x<<<(BX * D + 255) / 256, 256>>>(x1, x2);
    prep_w<<<dim3(16, 8, O), 256>>>(W_bil);
    comb_w<<<(2 * O * D + 255) / 256, 256>>>(W_bil, W_lin, b_lin, bw);
    A_terms_mma<<<dim3(8, 2), 256, GSMEM>>>();

    stage1_mma<<<dim3(8, 512), 256, GSMEM>>>();
    stage2_mma<<<dim3(2, BX), 256, GSMEM>>>(bw, out);
}